// round 6
// baseline (speedup 1.0000x reference)
#include <cuda_runtime.h>
#include <cuda_bf16.h>
#include <math.h>
#include <stdint.h>

// Problem dims
constexpr int NB  = 2;
constexpr int NS  = 1024;
constexpr int ND  = 512;
constexpr int NH  = 8;
constexpr int NDH = 64;
constexpr int NL  = 6;
constexpr int NV  = 50257;
constexpr int NBS = NB * NS;      // 2048
constexpr int NFF = 4 * ND;       // 2048
constexpr float INV_SCALE = 0.04419417382415922f; // 1/sqrt(512)

// ---------------- scratch (static device globals; no allocation) -------------
__device__ float g_x[NBS * ND];
__device__ float g_h[NBS * ND];
__device__ float g_q[NBS * ND];
__device__ float g_k[NBS * ND];
__device__ float g_v[NBS * ND];
__device__ float g_o[NBS * ND];
__device__ float g_ff[NBS * NFF];
__device__ float g_nll[NBS];

__device__ __forceinline__ float to_tf32(float x) {
    uint32_t u;
    asm("cvt.rna.tf32.f32 %0, %1;" : "=r"(u) : "f"(x));
    return __uint_as_float(u);
}

// ---------------- embedding --------------------------------------------------
__global__ void embed_k(const int* __restrict__ idx, const int* __restrict__ mask,
                        const float* __restrict__ tok, const float* __restrict__ pos,
                        float* __restrict__ x) {
    int row = blockIdx.x;               // b*NS + s
    int b = row / NS, s = row % NS;
    int t = idx[b * (NS + 1) + s];
    float m = (float)mask[row];
    const float* tr = tok + (size_t)t * ND;
    const float* pr = pos + (size_t)s * ND;
    float* xr = x + (size_t)row * ND;
    for (int d = threadIdx.x; d < ND; d += blockDim.x)
        xr[d] = (tr[d] + pr[d]) * m;
}

// ---------------- layernorm --------------------------------------------------
__global__ __launch_bounds__(256) void ln_k(const float* __restrict__ x,
                                            const float* __restrict__ g,
                                            const float* __restrict__ be,
                                            float* __restrict__ out) {
    int row = blockIdx.x;
    int tid = threadIdx.x;
    const float* xr = x + (size_t)row * ND;
    float v0 = xr[tid], v1 = xr[tid + 256];
    __shared__ float red[256];
    red[tid] = v0 + v1;
    __syncthreads();
    for (int o = 128; o > 0; o >>= 1) { if (tid < o) red[tid] += red[tid + o]; __syncthreads(); }
    float mean = red[0] * (1.0f / ND);
    __syncthreads();
    float d0 = v0 - mean, d1 = v1 - mean;
    red[tid] = d0 * d0 + d1 * d1;
    __syncthreads();
    for (int o = 128; o > 0; o >>= 1) { if (tid < o) red[tid] += red[tid + o]; __syncthreads(); }
    float inv = rsqrtf(red[0] * (1.0f / ND) + 1e-5f);
    float* orow = out + (size_t)row * ND;
    orow[tid]       = d0 * inv * g[tid]       + be[tid];
    orow[tid + 256] = d1 * inv * g[tid + 256] + be[tid + 256];
}

// ---------------- TF32 tensor-core GEMM, double-buffered ---------------------
// C[M,N] = act(A[M,K] @ B[K,N] + bias) + Res
// BM=128, BK=16, 256 threads. 2-stage smem pipeline with register staging:
// next tile's LDGs are issued before the mma loop of the current tile.
template <int ACT, bool HAS_BIAS, bool HAS_RES, int BN, bool BALIGN>
__device__ __forceinline__ void gemm_body(const float* __restrict__ A,
                                          const float* __restrict__ Bm,
                                          const float* __restrict__ bias,
                                          const float* __restrict__ Res,
                                          float* __restrict__ C,
                                          int M, int N, int K,
                                          int m0, int n0) {
    constexpr int BM = 128, BK = 16;
    constexpr int WARPS_N = (BN == 128) ? 4 : 2;
    constexpr int WARPS_M = 8 / WARPS_N;
    constexpr int WM = BM / WARPS_M;          // 64 or 32
    constexpr int WN = BN / WARPS_N;          // 32
    constexpr int MT = WM / 16;               // 4 or 2
    constexpr int NT = WN / 8;                // 4

    __shared__ float As[2][BK][BM + 4];
    __shared__ float Bs[2][BK][BN + 4];

    int tid = threadIdx.x;
    int warp = tid >> 5;
    int lane = tid & 31;
    int g  = lane >> 2;
    int tg = lane & 3;
    int warpM = warp % WARPS_M;
    int warpN = warp / WARPS_M;

    float acc[MT][NT][4];
#pragma unroll
    for (int i = 0; i < MT; i++)
#pragma unroll
        for (int j = 0; j < NT; j++)
#pragma unroll
            for (int c = 0; c < 4; c++) acc[i][j][c] = 0.f;

    int arow = tid >> 1, ak = (tid & 1) * 8;
    // B indices
    int br128 = tid >> 5, bc128 = (tid & 31) * 4;
    int br64  = tid >> 4, bc64  = (tid & 15) * 4;

    float4 ra0, ra1, rb0, rb1;

    auto loadA = [&](int k0) {
        const float* ap = A + (size_t)(m0 + arow) * K + k0 + ak;
        ra0 = *(const float4*)ap;
        ra1 = *(const float4*)(ap + 4);
    };
    auto loadB = [&](int k0) {
        if (BN == 128) {
            if (BALIGN) {
                rb0 = *(const float4*)(Bm + (size_t)(k0 + br128) * N + n0 + bc128);
                rb1 = *(const float4*)(Bm + (size_t)(k0 + br128 + 8) * N + n0 + bc128);
            } else {
                const float* bp0 = Bm + (size_t)(k0 + br128) * N;
                const float* bp1 = Bm + (size_t)(k0 + br128 + 8) * N;
                int c0 = n0 + bc128;
                rb0.x = (c0 + 0 < N) ? bp0[c0 + 0] : 0.f;
                rb0.y = (c0 + 1 < N) ? bp0[c0 + 1] : 0.f;
                rb0.z = (c0 + 2 < N) ? bp0[c0 + 2] : 0.f;
                rb0.w = (c0 + 3 < N) ? bp0[c0 + 3] : 0.f;
                rb1.x = (c0 + 0 < N) ? bp1[c0 + 0] : 0.f;
                rb1.y = (c0 + 1 < N) ? bp1[c0 + 1] : 0.f;
                rb1.z = (c0 + 2 < N) ? bp1[c0 + 2] : 0.f;
                rb1.w = (c0 + 3 < N) ? bp1[c0 + 3] : 0.f;
            }
        } else {
            rb0 = *(const float4*)(Bm + (size_t)(k0 + br64) * N + n0 + bc64);
        }
    };
    auto storeA = [&](int s) {
        As[s][ak + 0][arow] = to_tf32(ra0.x); As[s][ak + 1][arow] = to_tf32(ra0.y);
        As[s][ak + 2][arow] = to_tf32(ra0.z); As[s][ak + 3][arow] = to_tf32(ra0.w);
        As[s][ak + 4][arow] = to_tf32(ra1.x); As[s][ak + 5][arow] = to_tf32(ra1.y);
        As[s][ak + 6][arow] = to_tf32(ra1.z); As[s][ak + 7][arow] = to_tf32(ra1.w);
    };
    auto storeB = [&](int s) {
        if (BN == 128) {
            Bs[s][br128][bc128 + 0] = to_tf32(rb0.x); Bs[s][br128][bc128 + 1] = to_tf32(rb0.y);
            Bs[s][br128][bc128 + 2] = to_tf32(rb0.z); Bs[s][br128][bc128 + 3] = to_tf32(rb0.w);
            Bs[s][br128 + 8][bc128 + 0] = to_tf32(rb1.x); Bs[s][br128 + 8][bc128 + 1] = to_tf32(rb1.y);
            Bs[s][br128 + 8][bc128 + 2] = to_tf32(rb1.z); Bs[s][br128 + 8][bc128 + 3] = to_tf32(rb1.w);
        } else {
            Bs[s][br64][bc64 + 0] = to_tf32(rb0.x); Bs[s][br64][bc64 + 1] = to_tf32(rb0.y);
            Bs[s][br64][bc64 + 2] = to_tf32(rb0.z); Bs[s][br64][bc64 + 3] = to_tf32(rb0.w);
        }
    };

    int nTiles = K / BK;
    loadA(0); loadB(0);
    storeA(0); storeB(0);
    __syncthreads();

    for (int t = 0; t < nTiles; t++) {
        int cur = t & 1, nxt = cur ^ 1;
        bool more = (t + 1 < nTiles);
        if (more) { loadA((t + 1) * BK); loadB((t + 1) * BK); }

#pragma unroll
        for (int kk = 0; kk < BK; kk += 8) {
            uint32_t afr[MT][4], bfr[NT][2];
#pragma unroll
            for (int mt = 0; mt < MT; mt++) {
                int r = warpM * WM + mt * 16 + g;
                afr[mt][0] = __float_as_uint(As[cur][kk + tg][r]);
                afr[mt][1] = __float_as_uint(As[cur][kk + tg][r + 8]);
                afr[mt][2] = __float_as_uint(As[cur][kk + tg + 4][r]);
                afr[mt][3] = __float_as_uint(As[cur][kk + tg + 4][r + 8]);
            }
#pragma unroll
            for (int nt = 0; nt < NT; nt++) {
                int cc = warpN * WN + nt * 8 + g;
                bfr[nt][0] = __float_as_uint(Bs[cur][kk + tg][cc]);
                bfr[nt][1] = __float_as_uint(Bs[cur][kk + tg + 4][cc]);
            }
#pragma unroll
            for (int mt = 0; mt < MT; mt++)
#pragma unroll
                for (int nt = 0; nt < NT; nt++) {
                    asm volatile(
                        "mma.sync.aligned.m16n8k8.row.col.f32.tf32.tf32.f32 "
                        "{%0,%1,%2,%3}, {%4,%5,%6,%7}, {%8,%9}, {%0,%1,%2,%3};"
                        : "+f"(acc[mt][nt][0]), "+f"(acc[mt][nt][1]),
                          "+f"(acc[mt][nt][2]), "+f"(acc[mt][nt][3])
                        : "r"(afr[mt][0]), "r"(afr[mt][1]),
                          "r"(afr[mt][2]), "r"(afr[mt][3]),
                          "r"(bfr[nt][0]), "r"(bfr[nt][1]));
                }
        }
        if (more) { storeA(nxt); storeB(nxt); }
        __syncthreads();
    }

    // --- epilogue ---
#pragma unroll
    for (int mt = 0; mt < MT; mt++) {
#pragma unroll
        for (int nt = 0; nt < NT; nt++) {
            int row0 = m0 + warpM * WM + mt * 16 + g;
            int col0 = n0 + warpN * WN + nt * 8 + 2 * tg;
#pragma unroll
            for (int hh = 0; hh < 2; hh++) {
                int row = row0 + hh * 8;
#pragma unroll
                for (int j = 0; j < 2; j++) {
                    int col = col0 + j;
                    if (col < N) {
                        float v = acc[mt][nt][hh * 2 + j];
                        if (HAS_BIAS) v += bias[col];
                        if (ACT == 1) v = 0.5f * v * (1.0f + erff(v * 0.70710678118654752f));
                        if (HAS_RES) v += Res[(size_t)row * N + col];
                        C[(size_t)row * N + col] = v;
                    }
                }
            }
        }
    }
}

template <int ACT, bool HAS_BIAS, bool HAS_RES, int BN, bool BALIGN>
__global__ __launch_bounds__(256) void gemm_tc(const float* __restrict__ A,
                                               const float* __restrict__ Bm,
                                               const float* __restrict__ bias,
                                               const float* __restrict__ Res,
                                               float* __restrict__ C,
                                               int M, int N, int K) {
    gemm_body<ACT, HAS_BIAS, HAS_RES, BN, BALIGN>(
        A, Bm, bias, Res, C, M, N, K, blockIdx.y * 128, blockIdx.x * BN);
}

// Batched QKV: blockIdx.z selects (weight, bias, out). Same A.
struct TriPtrs {
    const float* w[3];
    const float* b[3];
    float*       c[3];
};
__global__ __launch_bounds__(256) void gemm_qkv(const float* __restrict__ A,
                                                TriPtrs t, int M, int N, int K) {
    int z = blockIdx.z;
    gemm_body<0, true, false, 64, true>(
        A, t.w[z], t.b[z], nullptr, t.c[z], M, N, K, blockIdx.y * 128, blockIdx.x * 64);
}

// ---------------- fused flash attention (fp32 SIMT) --------------------------
// grid (NS/64, NB*NH), 256 threads. Per CTA: 64 q-rows. k-blocks of 32.
// Thread: row = tid>>2 (0..63), sub = tid&3 (dims sub*16..sub*16+15).
// Scores: partial dot over own 16 dims, shfl-reduce over the 4 lanes of a row;
// all 32 p's live in registers -> no P smem, no Att matrix.
__global__ __launch_bounds__(256) void fa_k(const float* __restrict__ Q,
                                            const float* __restrict__ Kg,
                                            const float* __restrict__ Vg,
                                            float* __restrict__ O) {
    __shared__ float Ks[32][NDH + 4];
    __shared__ float Vs[32][NDH + 4];

    int q0 = (gridDim.x - 1 - blockIdx.x) * 64;   // longest blocks first
    int bh = blockIdx.y;
    int b = bh / NH, h = bh % NH;
    int tid = threadIdx.x;
    int row = tid >> 2;
    int sub = tid & 3;
    int qg = q0 + row;

    const float* qrow = Q + ((size_t)(b * NS + qg)) * ND + h * NDH + sub * 16;
    float4 q4[4];
#pragma unroll
    for (int j = 0; j < 4; j++) q4[j] = *(const float4*)(qrow + j * 4);

    const float* kbase = Kg + (size_t)b * NS * ND + h * NDH;
    const float* vbase = Vg + (size_t)b * NS * ND + h * NDH;

    int lrow = tid >> 3;            // 0..31
    int lcol = (tid & 7) * 8;       // 0..56

    float m_old = -INFINITY;
    float l = 0.f;
    float acc[16];
#pragma unroll
    for (int j = 0; j < 16; j++) acc[j] = 0.f;

    for (int kc = 0; kc < q0 + 64; kc += 32) {
        __syncthreads();
        {
            const float* kp = kbase + (size_t)(kc + lrow) * ND + lcol;
            const float* vp = vbase + (size_t)(kc + lrow) * ND + lcol;
            *(float4*)&Ks[lrow][lcol]     = *(const float4*)kp;
            *(float4*)&Ks[lrow][lcol + 4] = *(const float4*)(kp + 4);
            *(float4*)&Vs[lrow][lcol]     = *(const float4*)vp;
            *(float4*)&Vs[lrow][lcol + 4] = *(const float4*)(vp + 4);
        }
        __syncthreads();

        float s[32];
#pragma unroll
        for (int k = 0; k < 32; k++) {
            float4 k0 = *(float4*)&Ks[k][sub * 16];
            float4 k1 = *(float4*)&Ks[k][sub * 16 + 4];
            float4 k2 = *(float4*)&Ks[k][sub * 16 + 8];
            float4 k3 = *(float4*)&Ks[k][sub * 16 + 12];
            float d0 = q4[0].x * k0.x + q4[0].y * k0.y + q4[0].z * k0.z + q4[0].w * k0.w;
            float d1 = q4[1].x * k1.x + q4[1].y * k1.y + q4[1].z * k1.z + q4[1].w * k1.w;
            float d2 = q4[2].x * k2.x + q4[2].y * k2.y + q4[2].z * k2.z + q4[2].w * k2.w;
            float d3 = q4[3].x * k3.x + q4[3].y * k3.y + q4[3].z * k3.z + q4[3].w * k3.w;
            s[k] = (d0 + d1) + (d2 + d3);
        }
        // reduce partial dots across the 4 lanes of this row
#pragma unroll
        for (int k = 0; k < 32; k++) {
            s[k] += __shfl_xor_sync(0xffffffffu, s[k], 1);
            s[k] += __shfl_xor_sync(0xffffffffu, s[k], 2);
            int kg = kc + k;
            s[k] = (kg <= qg) ? s[k] * INV_SCALE : -INFINITY;
        }
        float m_blk = s[0];
#pragma unroll
        for (int k = 1; k < 32; k++) m_blk = fmaxf(m_blk, s[k]);
        float m_new = fmaxf(m_old, m_blk);
        float fac = __expf(m_old - m_new);
        float psum = 0.f;
#pragma unroll
        for (int k = 0; k < 32; k++) {
            s[k] = __expf(s[k] - m_new);
            psum += s[k];
        }
        l = l * fac + psum;
        m_old = m_new;
#pragma unroll
        for (int j = 0; j < 16; j++) acc[j] *= fac;
#pragma unroll
        for (int k = 0; k < 32; k++) {
            float pk = s[k];
            float4 v0 = *(float4*)&Vs[k][sub * 16];
            float4 v1 = *(float4*)&Vs[k][sub * 16 + 4];
            float4 v2 = *(float4*)&Vs[k][sub * 16 + 8];
            float4 v3 = *(float4*)&Vs[k][sub * 16 + 12];
            acc[0]  += pk * v0.x; acc[1]  += pk * v0.y; acc[2]  += pk * v0.z; acc[3]  += pk * v0.w;
            acc[4]  += pk * v1.x; acc[5]  += pk * v1.y; acc[6]  += pk * v1.z; acc[7]  += pk * v1.w;
            acc[8]  += pk * v2.x; acc[9]  += pk * v2.y; acc[10] += pk * v2.z; acc[11] += pk * v2.w;
            acc[12] += pk * v3.x; acc[13] += pk * v3.y; acc[14] += pk * v3.z; acc[15] += pk * v3.w;
        }
    }

    float inv = 1.0f / l;
    float* orow = O + ((size_t)(b * NS + qg)) * ND + h * NDH + sub * 16;
#pragma unroll
    for (int j = 0; j < 4; j++) {
        float4 r4 = make_float4(acc[j * 4] * inv, acc[j * 4 + 1] * inv,
                                acc[j * 4 + 2] * inv, acc[j * 4 + 3] * inv);
        *(float4*)(orow + j * 4) = r4;
    }
}

// ---------------- loss -------------------------------------------------------
__global__ __launch_bounds__(512) void loss_row_k(const float* __restrict__ logits,
                                                  const int* __restrict__ idx,
                                                  const int* __restrict__ mask,
                                                  float* __restrict__ nll) {
    int row = blockIdx.x;
    int b = row / NS, s = row % NS;
    const float* lr = logits + (size_t)row * NV;
    int tid = threadIdx.x;
    __shared__ float red[512];
    float mx = -3.4e38f;
    for (int i = tid; i < NV; i += 512) mx = fmaxf(mx, lr[i]);
    red[tid] = mx; __syncthreads();
    for (int o = 256; o > 0; o >>= 1) { if (tid < o) red[tid] = fmaxf(red[tid], red[tid + o]); __syncthreads(); }
    mx = red[0]; __syncthreads();
    float sum = 0.f;
    for (int i = tid; i < NV; i += 512) sum += __expf(lr[i] - mx);
    red[tid] = sum; __syncthreads();
    for (int o = 256; o > 0; o >>= 1) { if (tid < o) red[tid] += red[tid + o]; __syncthreads(); }
    if (tid == 0) {
        int tgt = idx[b * (NS + 1) + s + 1];
        float lse = mx + logf(red[0]);
        nll[row] = (lse - lr[tgt]) * (float)mask[row];
    }
}

__global__ __launch_bounds__(1024) void loss_final_k(const float* __restrict__ nll,
                                                     float* __restrict__ out) {
    __shared__ float red[1024];
    int tid = threadIdx.x;
    red[tid] = nll[tid] + nll[tid + 1024];
    __syncthreads();
    for (int o = 512; o > 0; o >>= 1) { if (tid < o) red[tid] += red[tid + o]; __syncthreads(); }
    if (tid == 0) out[0] = red[0] * (1.0f / (float)NBS);
}

// ---------------- host orchestration -----------------------------------------
extern "C" void kernel_launch(void* const* d_in, const int* in_sizes, int n_in,
                              void* d_out, int out_size) {
    const int*   idx  = (const int*)d_in[0];
    const int*   mask = (const int*)d_in[1];
    const float* tok  = (const float*)d_in[2];
    const float* pos  = (const float*)d_in[3];
    const float* Wq   = (const float*)d_in[4];
    const float* bq   = (const float*)d_in[5];
    const float* Wk   = (const float*)d_in[6];
    const float* bk   = (const float*)d_in[7];
    const float* Wv   = (const float*)d_in[8];
    const float* bv   = (const float*)d_in[9];
    const float* Wo   = (const float*)d_in[10];
    const float* bo   = (const float*)d_in[11];
    const float* ln1g = (const float*)d_in[12];
    const float* ln1b = (const float*)d_in[13];
    const float* W1   = (const float*)d_in[14];
    const float* b1   = (const float*)d_in[15];
    const float* W2   = (const float*)d_in[16];
    const float* b2   = (const float*)d_in[17];
    const float* ln2g = (const float*)d_in[18];
    const float* ln2b = (const float*)d_in[19];
    const float* lnfg = (const float*)d_in[20];
    const float* lnfb = (const float*)d_in[21];
    const float* headw= (const float*)d_in[22];
    float* out = (float*)d_out;

    float *x, *h, *q, *k, *v, *o, *ff, *nll;
    cudaGetSymbolAddress((void**)&x,   g_x);
    cudaGetSymbolAddress((void**)&h,   g_h);
    cudaGetSymbolAddress((void**)&q,   g_q);
    cudaGetSymbolAddress((void**)&k,   g_k);
    cudaGetSymbolAddress((void**)&v,   g_v);
    cudaGetSymbolAddress((void**)&o,   g_o);
    cudaGetSymbolAddress((void**)&ff,  g_ff);
    cudaGetSymbolAddress((void**)&nll, g_nll);

    embed_k<<<NBS, 256>>>(idx, mask, tok, pos, x);

    dim3 gQKV(ND / 64, NBS / 128, 3);   // 8 x 16 x 3 = 384 CTAs
    dim3 gDD(ND / 64, NBS / 128);       // 128 CTAs
    dim3 gDF(NFF / 128, NBS / 128);     // 256 CTAs
    dim3 gFA(NS / 64, NB * NH);         // 16 x 16 = 256 CTAs

    for (int l = 0; l < NL; l++) {
        const float* wq = Wq + (size_t)l * ND * ND;
        const float* wk = Wk + (size_t)l * ND * ND;
        const float* wv = Wv + (size_t)l * ND * ND;
        const float* wo = Wo + (size_t)l * ND * ND;
        const float* w1 = W1 + (size_t)l * ND * NFF;
        const float* w2 = W2 + (size_t)l * NFF * ND;

        ln_k<<<NBS, 256>>>(x, ln1g + l * ND, ln1b + l * ND, h);
        TriPtrs t;
        t.w[0] = wq; t.w[1] = wk; t.w[2] = wv;
        t.b[0] = bq + l * ND; t.b[1] = bk + l * ND; t.b[2] = bv + l * ND;
        t.c[0] = q; t.c[1] = k; t.c[2] = v;
        gemm_qkv<<<gQKV, 256>>>(h, t, NBS, ND, ND);
        fa_k<<<gFA, 256>>>(q, k, v, o);
        gemm_tc<0, true, true, 64, true><<<gDD, 256>>>(o, wo, bo + l * ND, x, x, NBS, ND, ND);
        ln_k<<<NBS, 256>>>(x, ln2g + l * ND, ln2b + l * ND, h);
        gemm_tc<1, true, false, 128, true><<<gDF, 256>>>(h, w1, b1 + l * NFF, nullptr, ff, NBS, NFF, ND);
        gemm_tc<0, true, true, 64, true><<<gDD, 256>>>(ff, w2, b2 + l * ND, x, x, NBS, ND, NFF);
    }

    ln_k<<<NBS, 256>>>(x, lnfg, lnfb, h);
    dim3 gHead((NV + 127) / 128, NBS / 128);
    gemm_tc<0, false, false, 128, false><<<gHead, 256>>>(h, headw, nullptr, nullptr, out, NBS, NV, ND);

    loss_row_k<<<NBS, 512>>>(out, idx, mask, nll);
    loss_final_k<<<1, 1024>>>(nll, out + (size_t)NBS * NV);
}

// round 7
// speedup vs baseline: 1.5870x; 1.5870x over previous
#include <cuda_runtime.h>
#include <cuda_bf16.h>
#include <math.h>
#include <stdint.h>

// Problem dims
constexpr int NB  = 2;
constexpr int NS  = 1024;
constexpr int ND  = 512;
constexpr int NH  = 8;
constexpr int NDH = 64;
constexpr int NL  = 6;
constexpr int NV  = 50257;
constexpr int NBS = NB * NS;      // 2048
constexpr int NFF = 4 * ND;       // 2048
constexpr float INV_SCALE = 0.04419417382415922f; // 1/sqrt(512)

// ---------------- scratch (static device globals; no allocation) -------------
__device__ float g_x[NBS * ND];
__device__ float g_h[NBS * ND];
__device__ float g_q[NBS * ND];
__device__ float g_k[NBS * ND];
__device__ float g_v[NBS * ND];
__device__ float g_o[NBS * ND];
__device__ float g_ff[NBS * NFF];
__device__ float g_att[(size_t)NB * NH * NS * NS];   // 64 MB
__device__ float g_nll[NBS];

__device__ __forceinline__ float to_tf32(float x) {
    uint32_t u;
    asm("cvt.rna.tf32.f32 %0, %1;" : "=r"(u) : "f"(x));
    return __uint_as_float(u);
}

// ---------------- embedding --------------------------------------------------
__global__ void embed_k(const int* __restrict__ idx, const int* __restrict__ mask,
                        const float* __restrict__ tok, const float* __restrict__ pos,
                        float* __restrict__ x) {
    int row = blockIdx.x;               // b*NS + s
    int b = row / NS, s = row % NS;
    int t = idx[b * (NS + 1) + s];
    float m = (float)mask[row];
    const float* tr = tok + (size_t)t * ND;
    const float* pr = pos + (size_t)s * ND;
    float* xr = x + (size_t)row * ND;
    for (int d = threadIdx.x; d < ND; d += blockDim.x)
        xr[d] = (tr[d] + pr[d]) * m;
}

// ---------------- layernorm --------------------------------------------------
__global__ __launch_bounds__(256) void ln_k(const float* __restrict__ x,
                                            const float* __restrict__ g,
                                            const float* __restrict__ be,
                                            float* __restrict__ out) {
    int row = blockIdx.x;
    int tid = threadIdx.x;
    const float* xr = x + (size_t)row * ND;
    float v0 = xr[tid], v1 = xr[tid + 256];
    __shared__ float red[256];
    red[tid] = v0 + v1;
    __syncthreads();
    for (int o = 128; o > 0; o >>= 1) { if (tid < o) red[tid] += red[tid + o]; __syncthreads(); }
    float mean = red[0] * (1.0f / ND);
    __syncthreads();
    float d0 = v0 - mean, d1 = v1 - mean;
    red[tid] = d0 * d0 + d1 * d1;
    __syncthreads();
    for (int o = 128; o > 0; o >>= 1) { if (tid < o) red[tid] += red[tid + o]; __syncthreads(); }
    float inv = rsqrtf(red[0] * (1.0f / ND) + 1e-5f);
    float* orow = out + (size_t)row * ND;
    orow[tid]       = d0 * inv * g[tid]       + be[tid];
    orow[tid + 256] = d1 * inv * g[tid + 256] + be[tid + 256];
}

// ---------------- TF32 tensor-core GEMM, double-buffered ---------------------
template <int ACT, bool HAS_BIAS, bool HAS_RES, int BN, bool BALIGN>
__device__ __forceinline__ void gemm_body(const float* __restrict__ A,
                                          const float* __restrict__ Bm,
                                          const float* __restrict__ bias,
                                          const float* __restrict__ Res,
                                          float* __restrict__ C,
                                          int M, int N, int K,
                                          int m0, int n0) {
    constexpr int BM = 128, BK = 16;
    constexpr int WARPS_N = (BN == 128) ? 4 : 2;
    constexpr int WARPS_M = 8 / WARPS_N;
    constexpr int WM = BM / WARPS_M;
    constexpr int WN = BN / WARPS_N;
    constexpr int MT = WM / 16;
    constexpr int NT = WN / 8;

    __shared__ float As[2][BK][BM + 4];
    __shared__ float Bs[2][BK][BN + 4];

    int tid = threadIdx.x;
    int warp = tid >> 5;
    int lane = tid & 31;
    int g  = lane >> 2;
    int tg = lane & 3;
    int warpM = warp % WARPS_M;
    int warpN = warp / WARPS_M;

    float acc[MT][NT][4];
#pragma unroll
    for (int i = 0; i < MT; i++)
#pragma unroll
        for (int j = 0; j < NT; j++)
#pragma unroll
            for (int c = 0; c < 4; c++) acc[i][j][c] = 0.f;

    int arow = tid >> 1, ak = (tid & 1) * 8;
    int br128 = tid >> 5, bc128 = (tid & 31) * 4;
    int br64  = tid >> 4, bc64  = (tid & 15) * 4;

    float4 ra0, ra1, rb0, rb1;

    auto loadA = [&](int k0) {
        const float* ap = A + (size_t)(m0 + arow) * K + k0 + ak;
        ra0 = *(const float4*)ap;
        ra1 = *(const float4*)(ap + 4);
    };
    auto loadB = [&](int k0) {
        if (BN == 128) {
            if (BALIGN) {
                rb0 = *(const float4*)(Bm + (size_t)(k0 + br128) * N + n0 + bc128);
                rb1 = *(const float4*)(Bm + (size_t)(k0 + br128 + 8) * N + n0 + bc128);
            } else {
                const float* bp0 = Bm + (size_t)(k0 + br128) * N;
                const float* bp1 = Bm + (size_t)(k0 + br128 + 8) * N;
                int c0 = n0 + bc128;
                rb0.x = (c0 + 0 < N) ? bp0[c0 + 0] : 0.f;
                rb0.y = (c0 + 1 < N) ? bp0[c0 + 1] : 0.f;
                rb0.z = (c0 + 2 < N) ? bp0[c0 + 2] : 0.f;
                rb0.w = (c0 + 3 < N) ? bp0[c0 + 3] : 0.f;
                rb1.x = (c0 + 0 < N) ? bp1[c0 + 0] : 0.f;
                rb1.y = (c0 + 1 < N) ? bp1[c0 + 1] : 0.f;
                rb1.z = (c0 + 2 < N) ? bp1[c0 + 2] : 0.f;
                rb1.w = (c0 + 3 < N) ? bp1[c0 + 3] : 0.f;
            }
        } else {
            rb0 = *(const float4*)(Bm + (size_t)(k0 + br64) * N + n0 + bc64);
        }
    };
    auto storeA = [&](int s) {
        As[s][ak + 0][arow] = to_tf32(ra0.x); As[s][ak + 1][arow] = to_tf32(ra0.y);
        As[s][ak + 2][arow] = to_tf32(ra0.z); As[s][ak + 3][arow] = to_tf32(ra0.w);
        As[s][ak + 4][arow] = to_tf32(ra1.x); As[s][ak + 5][arow] = to_tf32(ra1.y);
        As[s][ak + 6][arow] = to_tf32(ra1.z); As[s][ak + 7][arow] = to_tf32(ra1.w);
    };
    auto storeB = [&](int s) {
        if (BN == 128) {
            Bs[s][br128][bc128 + 0] = to_tf32(rb0.x); Bs[s][br128][bc128 + 1] = to_tf32(rb0.y);
            Bs[s][br128][bc128 + 2] = to_tf32(rb0.z); Bs[s][br128][bc128 + 3] = to_tf32(rb0.w);
            Bs[s][br128 + 8][bc128 + 0] = to_tf32(rb1.x); Bs[s][br128 + 8][bc128 + 1] = to_tf32(rb1.y);
            Bs[s][br128 + 8][bc128 + 2] = to_tf32(rb1.z); Bs[s][br128 + 8][bc128 + 3] = to_tf32(rb1.w);
        } else {
            Bs[s][br64][bc64 + 0] = to_tf32(rb0.x); Bs[s][br64][bc64 + 1] = to_tf32(rb0.y);
            Bs[s][br64][bc64 + 2] = to_tf32(rb0.z); Bs[s][br64][bc64 + 3] = to_tf32(rb0.w);
        }
    };

    int nTiles = K / BK;
    loadA(0); loadB(0);
    storeA(0); storeB(0);
    __syncthreads();

    for (int t = 0; t < nTiles; t++) {
        int cur = t & 1, nxt = cur ^ 1;
        bool more = (t + 1 < nTiles);
        if (more) { loadA((t + 1) * BK); loadB((t + 1) * BK); }

#pragma unroll
        for (int kk = 0; kk < BK; kk += 8) {
            uint32_t afr[MT][4], bfr[NT][2];
#pragma unroll
            for (int mt = 0; mt < MT; mt++) {
                int r = warpM * WM + mt * 16 + g;
                afr[mt][0] = __float_as_uint(As[cur][kk + tg][r]);
                afr[mt][1] = __float_as_uint(As[cur][kk + tg][r + 8]);
                afr[mt][2] = __float_as_uint(As[cur][kk + tg + 4][r]);
                afr[mt][3] = __float_as_uint(As[cur][kk + tg + 4][r + 8]);
            }
#pragma unroll
            for (int nt = 0; nt < NT; nt++) {
                int cc = warpN * WN + nt * 8 + g;
                bfr[nt][0] = __float_as_uint(Bs[cur][kk + tg][cc]);
                bfr[nt][1] = __float_as_uint(Bs[cur][kk + tg + 4][cc]);
            }
#pragma unroll
            for (int mt = 0; mt < MT; mt++)
#pragma unroll
                for (int nt = 0; nt < NT; nt++) {
                    asm volatile(
                        "mma.sync.aligned.m16n8k8.row.col.f32.tf32.tf32.f32 "
                        "{%0,%1,%2,%3}, {%4,%5,%6,%7}, {%8,%9}, {%0,%1,%2,%3};"
                        : "+f"(acc[mt][nt][0]), "+f"(acc[mt][nt][1]),
                          "+f"(acc[mt][nt][2]), "+f"(acc[mt][nt][3])
                        : "r"(afr[mt][0]), "r"(afr[mt][1]),
                          "r"(afr[mt][2]), "r"(afr[mt][3]),
                          "r"(bfr[nt][0]), "r"(bfr[nt][1]));
                }
        }
        if (more) { storeA(nxt); storeB(nxt); }
        __syncthreads();
    }

#pragma unroll
    for (int mt = 0; mt < MT; mt++) {
#pragma unroll
        for (int nt = 0; nt < NT; nt++) {
            int row0 = m0 + warpM * WM + mt * 16 + g;
            int col0 = n0 + warpN * WN + nt * 8 + 2 * tg;
#pragma unroll
            for (int hh = 0; hh < 2; hh++) {
                int row = row0 + hh * 8;
#pragma unroll
                for (int j = 0; j < 2; j++) {
                    int col = col0 + j;
                    if (col < N) {
                        float v = acc[mt][nt][hh * 2 + j];
                        if (HAS_BIAS) v += bias[col];
                        if (ACT == 1) v = 0.5f * v * (1.0f + erff(v * 0.70710678118654752f));
                        if (HAS_RES) v += Res[(size_t)row * N + col];
                        C[(size_t)row * N + col] = v;
                    }
                }
            }
        }
    }
}

template <int ACT, bool HAS_BIAS, bool HAS_RES, int BN, bool BALIGN>
__global__ __launch_bounds__(256) void gemm_tc(const float* __restrict__ A,
                                               const float* __restrict__ Bm,
                                               const float* __restrict__ bias,
                                               const float* __restrict__ Res,
                                               float* __restrict__ C,
                                               int M, int N, int K) {
    gemm_body<ACT, HAS_BIAS, HAS_RES, BN, BALIGN>(
        A, Bm, bias, Res, C, M, N, K, blockIdx.y * 128, blockIdx.x * BN);
}

struct TriPtrs {
    const float* w[3];
    const float* b[3];
    float*       c[3];
};
__global__ __launch_bounds__(256) void gemm_qkv(const float* __restrict__ A,
                                                TriPtrs t, int M, int N, int K) {
    int z = blockIdx.z;
    gemm_body<0, true, false, 64, true>(
        A, t.w[z], t.b[z], nullptr, t.c[z], M, N, K, blockIdx.y * 128, blockIdx.x * 64);
}

// ---------------- QK^T via mma: 64x64 tiles, lower-triangular only -----------
// grid (136, NB*NH), 128 threads (4 warps). K=NDH=64.
__global__ __launch_bounds__(128) void qk_mma(const float* __restrict__ Q,
                                              const float* __restrict__ Kg,
                                              float* __restrict__ Att) {
    __shared__ float As[NDH][68];   // [k][m] Q tile transposed
    __shared__ float Bs[NDH][68];   // [k][n] K tile transposed

    int i = blockIdx.x;
    int qt = (int)((sqrtf(8.f * i + 1.f) - 1.f) * 0.5f);
    while ((qt + 1) * (qt + 2) / 2 <= i) qt++;
    while (qt * (qt + 1) / 2 > i) qt--;
    int kt = i - qt * (qt + 1) / 2;
    int q0 = qt * 64, k0 = kt * 64;
    int bh = blockIdx.y;
    int b = bh >> 3, h = bh & 7;

    int tid = threadIdx.x;
    int row = tid >> 1;            // 0..63
    int koff = (tid & 1) * 32;

    {
        const float* qp = Q + ((size_t)(b * NS + q0 + row)) * ND + h * NDH + koff;
        const float* kp = Kg + ((size_t)(b * NS + k0 + row)) * ND + h * NDH + koff;
#pragma unroll
        for (int j = 0; j < 8; j++) {
            float4 f = *(const float4*)(qp + j * 4);
            As[koff + j * 4 + 0][row] = to_tf32(f.x);
            As[koff + j * 4 + 1][row] = to_tf32(f.y);
            As[koff + j * 4 + 2][row] = to_tf32(f.z);
            As[koff + j * 4 + 3][row] = to_tf32(f.w);
            float4 g4 = *(const float4*)(kp + j * 4);
            Bs[koff + j * 4 + 0][row] = to_tf32(g4.x);
            Bs[koff + j * 4 + 1][row] = to_tf32(g4.y);
            Bs[koff + j * 4 + 2][row] = to_tf32(g4.z);
            Bs[koff + j * 4 + 3][row] = to_tf32(g4.w);
        }
    }
    __syncthreads();

    int warp = tid >> 5;
    int lane = tid & 31;
    int g = lane >> 2, tg = lane & 3;
    int m0 = warp * 16;

    float acc[8][4];
#pragma unroll
    for (int nt = 0; nt < 8; nt++)
#pragma unroll
        for (int c = 0; c < 4; c++) acc[nt][c] = 0.f;

#pragma unroll
    for (int ks = 0; ks < 8; ks++) {
        int kk = ks * 8;
        uint32_t a0 = __float_as_uint(As[kk + tg][m0 + g]);
        uint32_t a1 = __float_as_uint(As[kk + tg][m0 + g + 8]);
        uint32_t a2 = __float_as_uint(As[kk + tg + 4][m0 + g]);
        uint32_t a3 = __float_as_uint(As[kk + tg + 4][m0 + g + 8]);
#pragma unroll
        for (int nt = 0; nt < 8; nt++) {
            uint32_t b0 = __float_as_uint(Bs[kk + tg][nt * 8 + g]);
            uint32_t b1 = __float_as_uint(Bs[kk + tg + 4][nt * 8 + g]);
            asm volatile(
                "mma.sync.aligned.m16n8k8.row.col.f32.tf32.tf32.f32 "
                "{%0,%1,%2,%3}, {%4,%5,%6,%7}, {%8,%9}, {%0,%1,%2,%3};"
                : "+f"(acc[nt][0]), "+f"(acc[nt][1]), "+f"(acc[nt][2]), "+f"(acc[nt][3])
                : "r"(a0), "r"(a1), "r"(a2), "r"(a3), "r"(b0), "r"(b1));
        }
    }

#pragma unroll
    for (int nt = 0; nt < 8; nt++) {
#pragma unroll
        for (int hh = 0; hh < 2; hh++) {
            int q = q0 + m0 + g + hh * 8;
#pragma unroll
            for (int j = 0; j < 2; j++) {
                int k = k0 + nt * 8 + 2 * tg + j;
                float v = (k <= q) ? acc[nt][hh * 2 + j] * INV_SCALE : -INFINITY;
                Att[((size_t)bh * NS + q) * NS + k] = v;
            }
        }
    }
}

// ---------------- softmax: register-cached row, single exp -------------------
// Reads only k <= q (valid region); writes full NS row (zeros above diagonal).
__global__ __launch_bounds__(256) void softmax_k(float* __restrict__ Att) {
    int row = blockIdx.x;
    int q = row % NS;
    float* a = Att + (size_t)row * NS;
    int n = q + 1;
    int tid = threadIdx.x;
    __shared__ float red[256];
    float vals[4];
#pragma unroll
    for (int j = 0; j < 4; j++) {
        int i = tid + j * 256;
        vals[j] = (i < n) ? a[i] : -INFINITY;
    }
    float mx = fmaxf(fmaxf(vals[0], vals[1]), fmaxf(vals[2], vals[3]));
    red[tid] = mx; __syncthreads();
    for (int o = 128; o > 0; o >>= 1) { if (tid < o) red[tid] = fmaxf(red[tid], red[tid + o]); __syncthreads(); }
    mx = red[0]; __syncthreads();
    float sum = 0.f;
#pragma unroll
    for (int j = 0; j < 4; j++) {
        vals[j] = __expf(vals[j] - mx);   // exp(-inf)=0
        sum += vals[j];
    }
    red[tid] = sum; __syncthreads();
    for (int o = 128; o > 0; o >>= 1) { if (tid < o) red[tid] += red[tid + o]; __syncthreads(); }
    float inv = 1.0f / red[0];
#pragma unroll
    for (int j = 0; j < 4; j++) a[tid + j * 256] = vals[j] * inv;
}

// ---------------- P @ V via mma: 64(q) x 64(d), K to diagonal ----------------
// grid (NS/64, NB*NH), 128 threads (4 warps). BK=32.
__global__ __launch_bounds__(128) void av_mma(const float* __restrict__ Att,
                                              const float* __restrict__ Vg,
                                              float* __restrict__ O) {
    __shared__ float As[32][68];   // [k][m] P tile transposed
    __shared__ float Bs[32][68];   // [k][n] V tile

    int q0 = blockIdx.x * 64;
    int bh = blockIdx.y;
    int b = bh >> 3, h = bh & 7;
    int tid = threadIdx.x;

    int prow = tid >> 1;              // 0..63
    int pkoff = (tid & 1) * 16;
    int vrow = tid >> 2;              // 0..31
    int vnoff = (tid & 3) * 16;

    const float* abase = Att + (size_t)bh * NS * NS;
    const float* vbase = Vg + (size_t)b * NS * ND + h * NDH;

    int warp = tid >> 5;
    int lane = tid & 31;
    int g = lane >> 2, tg = lane & 3;
    int m0 = warp * 16;

    float acc[8][4];
#pragma unroll
    for (int nt = 0; nt < 8; nt++)
#pragma unroll
        for (int c = 0; c < 4; c++) acc[nt][c] = 0.f;

    for (int kc = 0; kc < q0 + 64; kc += 32) {
        {
            const float* pp = abase + (size_t)(q0 + prow) * NS + kc + pkoff;
#pragma unroll
            for (int j = 0; j < 4; j++) {
                float4 f = *(const float4*)(pp + j * 4);
                As[pkoff + j * 4 + 0][prow] = to_tf32(f.x);
                As[pkoff + j * 4 + 1][prow] = to_tf32(f.y);
                As[pkoff + j * 4 + 2][prow] = to_tf32(f.z);
                As[pkoff + j * 4 + 3][prow] = to_tf32(f.w);
            }
            const float* vp = vbase + (size_t)(kc + vrow) * ND + vnoff;
#pragma unroll
            for (int j = 0; j < 4; j++) {
                float4 f = *(const float4*)(vp + j * 4);
                Bs[vrow][vnoff + j * 4 + 0] = to_tf32(f.x);
                Bs[vrow][vnoff + j * 4 + 1] = to_tf32(f.y);
                Bs[vrow][vnoff + j * 4 + 2] = to_tf32(f.z);
                Bs[vrow][vnoff + j * 4 + 3] = to_tf32(f.w);
            }
        }
        __syncthreads();

#pragma unroll
        for (int ks = 0; ks < 4; ks++) {
            int kk = ks * 8;
            uint32_t a0 = __float_as_uint(As[kk + tg][m0 + g]);
            uint32_t a1 = __float_as_uint(As[kk + tg][m0 + g + 8]);
            uint32_t a2 = __float_as_uint(As[kk + tg + 4][m0 + g]);
            uint32_t a3 = __float_as_uint(As[kk + tg + 4][m0 + g + 8]);
#pragma unroll
            for (int nt = 0; nt < 8; nt++) {
                uint32_t b0 = __float_as_uint(Bs[kk + tg][nt * 8 + g]);
                uint32_t b1 = __float_as_uint(Bs[kk + tg + 4][nt * 8 + g]);
                asm volatile(
                    "mma.sync.aligned.m16n8k8.row.col.f32.tf32.tf32.f32 "
                    "{%0,%1,%2,%3}, {%4,%5,%6,%7}, {%8,%9}, {%0,%1,%2,%3};"
                    : "+f"(acc[nt][0]), "+f"(acc[nt][1]), "+f"(acc[nt][2]), "+f"(acc[nt][3])
                    : "r"(a0), "r"(a1), "r"(a2), "r"(a3), "r"(b0), "r"(b1));
            }
        }
        __syncthreads();
    }

#pragma unroll
    for (int nt = 0; nt < 8; nt++) {
#pragma unroll
        for (int hh = 0; hh < 2; hh++) {
            int q = q0 + m0 + g + hh * 8;
#pragma unroll
            for (int j = 0; j < 2; j++) {
                int d = nt * 8 + 2 * tg + j;
                O[((size_t)(b * NS + q)) * ND + h * NDH + d] = acc[nt][hh * 2 + j];
            }
        }
    }
}

// ---------------- loss -------------------------------------------------------
__global__ __launch_bounds__(512) void loss_row_k(const float* __restrict__ logits,
                                                  const int* __restrict__ idx,
                                                  const int* __restrict__ mask,
                                                  float* __restrict__ nll) {
    int row = blockIdx.x;
    int b = row / NS, s = row % NS;
    const float* lr = logits + (size_t)row * NV;
    int tid = threadIdx.x;
    __shared__ float red[512];
    float mx = -3.4e38f;
    for (int i = tid; i < NV; i += 512) mx = fmaxf(mx, lr[i]);
    red[tid] = mx; __syncthreads();
    for (int o = 256; o > 0; o >>= 1) { if (tid < o) red[tid] = fmaxf(red[tid], red[tid + o]); __syncthreads(); }
    mx = red[0]; __syncthreads();
    float sum = 0.f;
    for (int i = tid; i < NV; i += 512) sum += __expf(lr[i] - mx);
    red[tid] = sum; __syncthreads();
    for (int o = 256; o > 0; o >>= 1) { if (tid < o) red[tid] += red[tid + o]; __syncthreads(); }
    if (tid == 0) {
        int tgt = idx[b * (NS + 1) + s + 1];
        float lse = mx + logf(red[0]);
        nll[row] = (lse - lr[tgt]) * (float)mask[row];
    }
}

__global__ __launch_bounds__(1024) void loss_final_k(const float* __restrict__ nll,
                                                     float* __restrict__ out) {
    __shared__ float red[1024];
    int tid = threadIdx.x;
    red[tid] = nll[tid] + nll[tid + 1024];
    __syncthreads();
    for (int o = 512; o > 0; o >>= 1) { if (tid < o) red[tid] += red[tid + o]; __syncthreads(); }
    if (tid == 0) out[0] = red[0] * (1.0f / (float)NBS);
}

// ---------------- host orchestration -----------------------------------------
extern "C" void kernel_launch(void* const* d_in, const int* in_sizes, int n_in,
                              void* d_out, int out_size) {
    const int*   idx  = (const int*)d_in[0];
    const int*   mask = (const int*)d_in[1];
    const float* tok  = (const float*)d_in[2];
    const float* pos  = (const float*)d_in[3];
    const float* Wq   = (const float*)d_in[4];
    const float* bq   = (const float*)d_in[5];
    const float* Wk   = (const float*)d_in[6];
    const float* bk   = (const float*)d_in[7];
    const float* Wv   = (const float*)d_in[8];
    const float* bv   = (const float*)d_in[9];
    const float* Wo   = (const float*)d_in[10];
    const float* bo   = (const float*)d_in[11];
    const float* ln1g = (const float*)d_in[12];
    const float* ln1b = (const float*)d_in[13];
    const float* W1   = (const float*)d_in[14];
    const float* b1   = (const float*)d_in[15];
    const float* W2   = (const float*)d_in[16];
    const float* b2   = (const float*)d_in[17];
    const float* ln2g = (const float*)d_in[18];
    const float* ln2b = (const float*)d_in[19];
    const float* lnfg = (const float*)d_in[20];
    const float* lnfb = (const float*)d_in[21];
    const float* headw= (const float*)d_in[22];
    float* out = (float*)d_out;

    float *x, *h, *q, *k, *v, *o, *ff, *att, *nll;
    cudaGetSymbolAddress((void**)&x,   g_x);
    cudaGetSymbolAddress((void**)&h,   g_h);
    cudaGetSymbolAddress((void**)&q,   g_q);
    cudaGetSymbolAddress((void**)&k,   g_k);
    cudaGetSymbolAddress((void**)&v,   g_v);
    cudaGetSymbolAddress((void**)&o,   g_o);
    cudaGetSymbolAddress((void**)&ff,  g_ff);
    cudaGetSymbolAddress((void**)&att, g_att);
    cudaGetSymbolAddress((void**)&nll, g_nll);

    embed_k<<<NBS, 256>>>(idx, mask, tok, pos, x);

    dim3 gQKV(ND / 64, NBS / 128, 3);   // 384 CTAs
    dim3 gDD(ND / 64, NBS / 128);       // 128 CTAs
    dim3 gDF(NFF / 128, NBS / 128);     // 256 CTAs
    dim3 gQK(136, NB * NH);             // lower-triangular 64x64 tiles
    dim3 gAV(NS / 64, NB * NH);         // 256 CTAs

    for (int l = 0; l < NL; l++) {
        const float* wq = Wq + (size_t)l * ND * ND;
        const float* wk = Wk + (size_t)l * ND * ND;
        const float* wv = Wv + (size_t)l * ND * ND;
        const float* wo = Wo + (size_t)l * ND * ND;
        const float* w1 = W1 + (size_t)l * ND * NFF;
        const float* w2 = W2 + (size_t)l * NFF * ND;

        ln_k<<<NBS, 256>>>(x, ln1g + l * ND, ln1b + l * ND, h);
        TriPtrs t;
        t.w[0] = wq; t.w[1] = wk; t.w[2] = wv;
        t.b[0] = bq + l * ND; t.b[1] = bk + l * ND; t.b[2] = bv + l * ND;
        t.c[0] = q; t.c[1] = k; t.c[2] = v;
        gemm_qkv<<<gQKV, 256>>>(h, t, NBS, ND, ND);
        qk_mma<<<gQK, 128>>>(q, k, att);
        softmax_k<<<NB * NH * NS, 256>>>(att);
        av_mma<<<gAV, 128>>>(att, v, o);
        gemm_tc<0, true, true, 64, true><<<gDD, 256>>>(o, wo, bo + l * ND, x, x, NBS, ND, ND);
        ln_k<<<NBS, 256>>>(x, ln2g + l * ND, ln2b + l * ND, h);
        gemm_tc<1, true, false, 128, true><<<gDF, 256>>>(h, w1, b1 + l * NFF, nullptr, ff, NBS, NFF, ND);
        gemm_tc<0, true, true, 64, true><<<gDD, 256>>>(ff, w2, b2 + l * ND, x, x, NBS, ND, NFF);
    }

    ln_k<<<NBS, 256>>>(x, lnfg, lnfb, h);
    dim3 gHead((NV + 127) / 128, NBS / 128);
    gemm_tc<0, false, false, 128, false><<<gHead, 256>>>(h, headw, nullptr, nullptr, out, NBS, NV, ND);

    loss_row_k<<<NBS, 512>>>(out, idx, mask, nll);
    loss_final_k<<<1, 1024>>>(nll, out + (size_t)NBS * NV);
}

// round 9
// speedup vs baseline: 1.8526x; 1.1673x over previous
#include <cuda_runtime.h>
#include <cuda_bf16.h>
#include <math.h>
#include <stdint.h>

// Problem dims
constexpr int NB  = 2;
constexpr int NS  = 1024;
constexpr int ND  = 512;
constexpr int NH  = 8;
constexpr int NDH = 64;
constexpr int NL  = 6;
constexpr int NV  = 50257;
constexpr int NBS = NB * NS;      // 2048
constexpr int NFF = 4 * ND;       // 2048
constexpr float INV_SCALE = 0.04419417382415922f; // 1/sqrt(512)

// ---------------- scratch (static device globals; no allocation) -------------
__device__ float g_x[NBS * ND];
__device__ float g_h[NBS * ND];
__device__ float g_q[NBS * ND];
__device__ float g_k[NBS * ND];
__device__ float g_v[NBS * ND];
__device__ float g_o[NBS * ND];
__device__ float g_ff[NBS * NFF];
__device__ float g_att[(size_t)NB * NH * NS * NS];   // 64 MB
__device__ float g_nll[NBS];

__device__ __forceinline__ float to_tf32(float x) {
    uint32_t u;
    asm("cvt.rna.tf32.f32 %0, %1;" : "=r"(u) : "f"(x));
    return __uint_as_float(u);
}

// Fragment-friendly column permutations.
// A rows (m, 16-block): a0/a1 = (g, g+8) adjacent; a2/a3 likewise.
__device__ __forceinline__ int ac16(int m) {
    return (m & ~15) | ((m & 7) << 1) | ((m >> 3) & 1);
}
// B cols (n, 32-block): b-regs for nt=0..3 at n=nt*8+g adjacent (float4).
__device__ __forceinline__ int bc32(int n) {
    return (n & ~31) | ((n & 7) << 2) | ((n >> 3) & 3);
}
// B cols (n, 64-block): nt=0..7 -> two float4.
__device__ __forceinline__ int bc64p(int n) {
    return ((n & 7) << 3) | ((n >> 3) & 7);
}

// ---------------- embedding --------------------------------------------------
__global__ void embed_k(const int* __restrict__ idx, const int* __restrict__ mask,
                        const float* __restrict__ tok, const float* __restrict__ pos,
                        float* __restrict__ x) {
    int row = blockIdx.x;
    int b = row / NS, s = row % NS;
    int t = idx[b * (NS + 1) + s];
    float m = (float)mask[row];
    const float* tr = tok + (size_t)t * ND;
    const float* pr = pos + (size_t)s * ND;
    float* xr = x + (size_t)row * ND;
    for (int d = threadIdx.x; d < ND; d += blockDim.x)
        xr[d] = (tr[d] + pr[d]) * m;
}

// ---------------- layernorm --------------------------------------------------
__global__ __launch_bounds__(256) void ln_k(const float* __restrict__ x,
                                            const float* __restrict__ g,
                                            const float* __restrict__ be,
                                            float* __restrict__ out) {
    int row = blockIdx.x;
    int tid = threadIdx.x;
    const float* xr = x + (size_t)row * ND;
    float v0 = xr[tid], v1 = xr[tid + 256];
    __shared__ float red[256];
    red[tid] = v0 + v1;
    __syncthreads();
    for (int o = 128; o > 0; o >>= 1) { if (tid < o) red[tid] += red[tid + o]; __syncthreads(); }
    float mean = red[0] * (1.0f / ND);
    __syncthreads();
    float d0 = v0 - mean, d1 = v1 - mean;
    red[tid] = d0 * d0 + d1 * d1;
    __syncthreads();
    for (int o = 128; o > 0; o >>= 1) { if (tid < o) red[tid] += red[tid + o]; __syncthreads(); }
    float inv = rsqrtf(red[0] * (1.0f / ND) + 1e-5f);
    float* orow = out + (size_t)row * ND;
    orow[tid]       = d0 * inv * g[tid]       + be[tid];
    orow[tid + 256] = d1 * inv * g[tid + 256] + be[tid + 256];
}

// ---------------- TF32 tensor-core GEMM, double-buffered, vectorized frags ---
template <int ACT, bool HAS_BIAS, bool HAS_RES, int BN, bool BALIGN>
__device__ __forceinline__ void gemm_body(const float* __restrict__ A,
                                          const float* __restrict__ Bm,
                                          const float* __restrict__ bias,
                                          const float* __restrict__ Res,
                                          float* __restrict__ C,
                                          int M, int N, int K,
                                          int m0, int n0) {
    constexpr int BM = 128, BK = 16;
    constexpr int WARPS_N = (BN == 128) ? 4 : 2;
    constexpr int WARPS_M = 8 / WARPS_N;
    constexpr int WM = BM / WARPS_M;          // 64 or 32
    constexpr int WN = BN / WARPS_N;          // 32
    constexpr int MT = WM / 16;               // 4 or 2
    constexpr int NT = WN / 8;                // 4
    constexpr int AP = BM + 8;                // pitch: tg*AP%32 == tg*8
    constexpr int BP = BN + 8;

    __shared__ float As[2][BK][AP];
    __shared__ float Bs[2][BK][BP];

    int tid = threadIdx.x;
    int warp = tid >> 5;
    int lane = tid & 31;
    int g  = lane >> 2;
    int tg = lane & 3;
    int warpM = warp % WARPS_M;
    int warpN = warp / WARPS_M;

    float acc[MT][NT][4];
#pragma unroll
    for (int i = 0; i < MT; i++)
#pragma unroll
        for (int j = 0; j < NT; j++)
#pragma unroll
            for (int c = 0; c < 4; c++) acc[i][j][c] = 0.f;

    int arow = tid >> 1, ak = (tid & 1) * 8;
    int acol = ac16(arow);
    int br128 = tid >> 5, bc128 = (tid & 31) * 4;
    int br64  = tid >> 4, bc64  = (tid & 15) * 4;

    float4 ra0, ra1, rb0, rb1;

    auto loadA = [&](int k0) {
        const float* ap = A + (size_t)(m0 + arow) * K + k0 + ak;
        ra0 = *(const float4*)ap;
        ra1 = *(const float4*)(ap + 4);
    };
    auto loadB = [&](int k0) {
        if (BN == 128) {
            if (BALIGN) {
                rb0 = *(const float4*)(Bm + (size_t)(k0 + br128) * N + n0 + bc128);
                rb1 = *(const float4*)(Bm + (size_t)(k0 + br128 + 8) * N + n0 + bc128);
            } else {
                const float* bp0 = Bm + (size_t)(k0 + br128) * N;
                const float* bp1 = Bm + (size_t)(k0 + br128 + 8) * N;
                int c0 = n0 + bc128;
                rb0.x = (c0 + 0 < N) ? bp0[c0 + 0] : 0.f;
                rb0.y = (c0 + 1 < N) ? bp0[c0 + 1] : 0.f;
                rb0.z = (c0 + 2 < N) ? bp0[c0 + 2] : 0.f;
                rb0.w = (c0 + 3 < N) ? bp0[c0 + 3] : 0.f;
                rb1.x = (c0 + 0 < N) ? bp1[c0 + 0] : 0.f;
                rb1.y = (c0 + 1 < N) ? bp1[c0 + 1] : 0.f;
                rb1.z = (c0 + 2 < N) ? bp1[c0 + 2] : 0.f;
                rb1.w = (c0 + 3 < N) ? bp1[c0 + 3] : 0.f;
            }
        } else {
            rb0 = *(const float4*)(Bm + (size_t)(k0 + br64) * N + n0 + bc64);
        }
    };
    auto storeA = [&](int s) {
        As[s][ak + 0][acol] = to_tf32(ra0.x); As[s][ak + 1][acol] = to_tf32(ra0.y);
        As[s][ak + 2][acol] = to_tf32(ra0.z); As[s][ak + 3][acol] = to_tf32(ra0.w);
        As[s][ak + 4][acol] = to_tf32(ra1.x); As[s][ak + 5][acol] = to_tf32(ra1.y);
        As[s][ak + 6][acol] = to_tf32(ra1.z); As[s][ak + 7][acol] = to_tf32(ra1.w);
    };
    auto storeB = [&](int s) {
        if (BN == 128) {
            Bs[s][br128][bc32(bc128 + 0)] = to_tf32(rb0.x);
            Bs[s][br128][bc32(bc128 + 1)] = to_tf32(rb0.y);
            Bs[s][br128][bc32(bc128 + 2)] = to_tf32(rb0.z);
            Bs[s][br128][bc32(bc128 + 3)] = to_tf32(rb0.w);
            Bs[s][br128 + 8][bc32(bc128 + 0)] = to_tf32(rb1.x);
            Bs[s][br128 + 8][bc32(bc128 + 1)] = to_tf32(rb1.y);
            Bs[s][br128 + 8][bc32(bc128 + 2)] = to_tf32(rb1.z);
            Bs[s][br128 + 8][bc32(bc128 + 3)] = to_tf32(rb1.w);
        } else {
            Bs[s][br64][bc32(bc64 + 0)] = to_tf32(rb0.x);
            Bs[s][br64][bc32(bc64 + 1)] = to_tf32(rb0.y);
            Bs[s][br64][bc32(bc64 + 2)] = to_tf32(rb0.z);
            Bs[s][br64][bc32(bc64 + 3)] = to_tf32(rb0.w);
        }
    };

    int nTiles = K / BK;
    loadA(0); loadB(0);
    storeA(0); storeB(0);
    __syncthreads();

    for (int t = 0; t < nTiles; t++) {
        int cur = t & 1, nxt = cur ^ 1;
        bool more = (t + 1 < nTiles);
        if (more) { loadA((t + 1) * BK); loadB((t + 1) * BK); }

#pragma unroll
        for (int kk = 0; kk < BK; kk += 8) {
            uint32_t afr[MT][4];
            float bfr0[NT], bfr1[NT];
#pragma unroll
            for (int mt = 0; mt < MT; mt++) {
                int mc = warpM * WM + mt * 16 + g * 2;
                float2 x0 = *(const float2*)&As[cur][kk + tg][mc];
                float2 x1 = *(const float2*)&As[cur][kk + tg + 4][mc];
                afr[mt][0] = __float_as_uint(x0.x);
                afr[mt][1] = __float_as_uint(x0.y);
                afr[mt][2] = __float_as_uint(x1.x);
                afr[mt][3] = __float_as_uint(x1.y);
            }
            {
                int nc = warpN * WN + g * 4;
                float4 b0 = *(const float4*)&Bs[cur][kk + tg][nc];
                float4 b1 = *(const float4*)&Bs[cur][kk + tg + 4][nc];
                bfr0[0] = b0.x; bfr0[1] = b0.y; bfr0[2] = b0.z; bfr0[3] = b0.w;
                bfr1[0] = b1.x; bfr1[1] = b1.y; bfr1[2] = b1.z; bfr1[3] = b1.w;
            }
#pragma unroll
            for (int mt = 0; mt < MT; mt++)
#pragma unroll
                for (int nt = 0; nt < NT; nt++) {
                    asm volatile(
                        "mma.sync.aligned.m16n8k8.row.col.f32.tf32.tf32.f32 "
                        "{%0,%1,%2,%3}, {%4,%5,%6,%7}, {%8,%9}, {%0,%1,%2,%3};"
                        : "+f"(acc[mt][nt][0]), "+f"(acc[mt][nt][1]),
                          "+f"(acc[mt][nt][2]), "+f"(acc[mt][nt][3])
                        : "r"(afr[mt][0]), "r"(afr[mt][1]),
                          "r"(afr[mt][2]), "r"(afr[mt][3]),
                          "r"(__float_as_uint(bfr0[nt])), "r"(__float_as_uint(bfr1[nt])));
                }
        }
        if (more) { storeA(nxt); storeB(nxt); }
        __syncthreads();
    }

#pragma unroll
    for (int mt = 0; mt < MT; mt++) {
#pragma unroll
        for (int nt = 0; nt < NT; nt++) {
            int row0 = m0 + warpM * WM + mt * 16 + g;
            int col0 = n0 + warpN * WN + nt * 8 + 2 * tg;
#pragma unroll
            for (int hh = 0; hh < 2; hh++) {
                int row = row0 + hh * 8;
#pragma unroll
                for (int j = 0; j < 2; j++) {
                    int col = col0 + j;
                    if (col < N) {
                        float v = acc[mt][nt][hh * 2 + j];
                        if (HAS_BIAS) v += bias[col];
                        if (ACT == 1) v = 0.5f * v * (1.0f + erff(v * 0.70710678118654752f));
                        if (HAS_RES) v += Res[(size_t)row * N + col];
                        C[(size_t)row * N + col] = v;
                    }
                }
            }
        }
    }
}

template <int ACT, bool HAS_BIAS, bool HAS_RES, int BN, bool BALIGN>
__global__ __launch_bounds__(256) void gemm_tc(const float* __restrict__ A,
                                               const float* __restrict__ Bm,
                                               const float* __restrict__ bias,
                                               const float* __restrict__ Res,
                                               float* __restrict__ C,
                                               int M, int N, int K) {
    gemm_body<ACT, HAS_BIAS, HAS_RES, BN, BALIGN>(
        A, Bm, bias, Res, C, M, N, K, blockIdx.y * 128, blockIdx.x * BN);
}

struct TriPtrs {
    const float* w[3];
    const float* b[3];
    float*       c[3];
};
__global__ __launch_bounds__(256) void gemm_qkv(const float* __restrict__ A,
                                                TriPtrs t, int M, int N, int K) {
    int z = blockIdx.z;
    gemm_body<0, true, false, 64, true>(
        A, t.w[z], t.b[z], nullptr, t.c[z], M, N, K, blockIdx.y * 128, blockIdx.x * 64);
}

// ---------------- QK^T via mma: 64x64 tiles, lower-triangular only -----------
__global__ __launch_bounds__(128) void qk_mma(const float* __restrict__ Q,
                                              const float* __restrict__ Kg,
                                              float* __restrict__ Att) {
    __shared__ float As[NDH][72];   // [k][ac16(m)] Q tile
    __shared__ float Bs[NDH][72];   // [k][bc64p(n)] K tile

    int i = blockIdx.x;
    int qt = (int)((sqrtf(8.f * i + 1.f) - 1.f) * 0.5f);
    while ((qt + 1) * (qt + 2) / 2 <= i) qt++;
    while (qt * (qt + 1) / 2 > i) qt--;
    int kt = i - qt * (qt + 1) / 2;
    int q0 = qt * 64, k0 = kt * 64;
    int bh = blockIdx.y;
    int b = bh >> 3, h = bh & 7;

    int tid = threadIdx.x;
    int row = tid >> 1;            // 0..63
    int koff = (tid & 1) * 32;
    int acol = ac16(row);
    int bcol = bc64p(row);

    {
        const float* qp = Q + ((size_t)(b * NS + q0 + row)) * ND + h * NDH + koff;
        const float* kp = Kg + ((size_t)(b * NS + k0 + row)) * ND + h * NDH + koff;
#pragma unroll
        for (int j = 0; j < 8; j++) {
            float4 f = *(const float4*)(qp + j * 4);
            As[koff + j * 4 + 0][acol] = to_tf32(f.x);
            As[koff + j * 4 + 1][acol] = to_tf32(f.y);
            As[koff + j * 4 + 2][acol] = to_tf32(f.z);
            As[koff + j * 4 + 3][acol] = to_tf32(f.w);
            float4 g4 = *(const float4*)(kp + j * 4);
            Bs[koff + j * 4 + 0][bcol] = to_tf32(g4.x);
            Bs[koff + j * 4 + 1][bcol] = to_tf32(g4.y);
            Bs[koff + j * 4 + 2][bcol] = to_tf32(g4.z);
            Bs[koff + j * 4 + 3][bcol] = to_tf32(g4.w);
        }
    }
    __syncthreads();

    int warp = tid >> 5;
    int lane = tid & 31;
    int g = lane >> 2, tg = lane & 3;
    int m0 = warp * 16;

    float acc[8][4];
#pragma unroll
    for (int nt = 0; nt < 8; nt++)
#pragma unroll
        for (int c = 0; c < 4; c++) acc[nt][c] = 0.f;

#pragma unroll
    for (int ks = 0; ks < 8; ks++) {
        int kk = ks * 8;
        float2 x0 = *(const float2*)&As[kk + tg][m0 + g * 2];
        float2 x1 = *(const float2*)&As[kk + tg + 4][m0 + g * 2];
        uint32_t a0 = __float_as_uint(x0.x), a1 = __float_as_uint(x0.y);
        uint32_t a2 = __float_as_uint(x1.x), a3 = __float_as_uint(x1.y);
        float4 b0lo = *(const float4*)&Bs[kk + tg][g * 8];
        float4 b0hi = *(const float4*)&Bs[kk + tg][g * 8 + 4];
        float4 b1lo = *(const float4*)&Bs[kk + tg + 4][g * 8];
        float4 b1hi = *(const float4*)&Bs[kk + tg + 4][g * 8 + 4];
        float bf0[8] = {b0lo.x, b0lo.y, b0lo.z, b0lo.w, b0hi.x, b0hi.y, b0hi.z, b0hi.w};
        float bf1[8] = {b1lo.x, b1lo.y, b1lo.z, b1lo.w, b1hi.x, b1hi.y, b1hi.z, b1hi.w};
#pragma unroll
        for (int nt = 0; nt < 8; nt++) {
            asm volatile(
                "mma.sync.aligned.m16n8k8.row.col.f32.tf32.tf32.f32 "
                "{%0,%1,%2,%3}, {%4,%5,%6,%7}, {%8,%9}, {%0,%1,%2,%3};"
                : "+f"(acc[nt][0]), "+f"(acc[nt][1]), "+f"(acc[nt][2]), "+f"(acc[nt][3])
                : "r"(a0), "r"(a1), "r"(a2), "r"(a3),
                  "r"(__float_as_uint(bf0[nt])), "r"(__float_as_uint(bf1[nt])));
        }
    }

#pragma unroll
    for (int nt = 0; nt < 8; nt++) {
#pragma unroll
        for (int hh = 0; hh < 2; hh++) {
            int q = q0 + m0 + g + hh * 8;
#pragma unroll
            for (int j = 0; j < 2; j++) {
                int k = k0 + nt * 8 + 2 * tg + j;
                float v = (k <= q) ? acc[nt][hh * 2 + j] * INV_SCALE : -INFINITY;
                Att[((size_t)bh * NS + q) * NS + k] = v;
            }
        }
    }
}

// ---------------- softmax: register-cached row, single exp -------------------
__global__ __launch_bounds__(256) void softmax_k(float* __restrict__ Att) {
    int row = blockIdx.x;
    int q = row % NS;
    float* a = Att + (size_t)row * NS;
    int n = q + 1;
    int tid = threadIdx.x;
    __shared__ float red[256];
    float vals[4];
#pragma unroll
    for (int j = 0; j < 4; j++) {
        int i = tid + j * 256;
        vals[j] = (i < n) ? a[i] : -INFINITY;
    }
    float mx = fmaxf(fmaxf(vals[0], vals[1]), fmaxf(vals[2], vals[3]));
    red[tid] = mx; __syncthreads();
    for (int o = 128; o > 0; o >>= 1) { if (tid < o) red[tid] = fmaxf(red[tid], red[tid + o]); __syncthreads(); }
    mx = red[0]; __syncthreads();
    float sum = 0.f;
#pragma unroll
    for (int j = 0; j < 4; j++) {
        vals[j] = __expf(vals[j] - mx);
        sum += vals[j];
    }
    red[tid] = sum; __syncthreads();
    for (int o = 128; o > 0; o >>= 1) { if (tid < o) red[tid] += red[tid + o]; __syncthreads(); }
    float inv = 1.0f / red[0];
#pragma unroll
    for (int j = 0; j < 4; j++) a[tid + j * 256] = vals[j] * inv;
}

// ---------------- P @ V via mma: 64(q) x 64(d), K to diagonal ----------------
__global__ __launch_bounds__(128) void av_mma(const float* __restrict__ Att,
                                              const float* __restrict__ Vg,
                                              float* __restrict__ O) {
    __shared__ float As[32][72];   // [k][ac16(m)] P tile
    __shared__ float Bs[32][72];   // [k][bc64p(n)] V tile

    int q0 = blockIdx.x * 64;
    int bh = blockIdx.y;
    int b = bh >> 3, h = bh & 7;
    int tid = threadIdx.x;

    int prow = tid >> 1;              // 0..63
    int pkoff = (tid & 1) * 16;
    int pacol = ac16(prow);
    int vrow = tid >> 2;              // 0..31
    int vnoff = (tid & 3) * 16;

    const float* abase = Att + (size_t)bh * NS * NS;
    const float* vbase = Vg + (size_t)b * NS * ND + h * NDH;

    int warp = tid >> 5;
    int lane = tid & 31;
    int g = lane >> 2, tg = lane & 3;
    int m0 = warp * 16;

    float acc[8][4];
#pragma unroll
    for (int nt = 0; nt < 8; nt++)
#pragma unroll
        for (int c = 0; c < 4; c++) acc[nt][c] = 0.f;

    for (int kc = 0; kc < q0 + 64; kc += 32) {
        {
            const float* pp = abase + (size_t)(q0 + prow) * NS + kc + pkoff;
#pragma unroll
            for (int j = 0; j < 4; j++) {
                float4 f = *(const float4*)(pp + j * 4);
                As[pkoff + j * 4 + 0][pacol] = to_tf32(f.x);
                As[pkoff + j * 4 + 1][pacol] = to_tf32(f.y);
                As[pkoff + j * 4 + 2][pacol] = to_tf32(f.z);
                As[pkoff + j * 4 + 3][pacol] = to_tf32(f.w);
            }
            const float* vp = vbase + (size_t)(kc + vrow) * ND + vnoff;
#pragma unroll
            for (int j = 0; j < 4; j++) {
                float4 f = *(const float4*)(vp + j * 4);
                Bs[vrow][bc64p(vnoff + j * 4 + 0)] = to_tf32(f.x);
                Bs[vrow][bc64p(vnoff + j * 4 + 1)] = to_tf32(f.y);
                Bs[vrow][bc64p(vnoff + j * 4 + 2)] = to_tf32(f.z);
                Bs[vrow][bc64p(vnoff + j * 4 + 3)] = to_tf32(f.w);
            }
        }
        __syncthreads();

#pragma unroll
        for (int ks = 0; ks < 4; ks++) {
            int kk = ks * 8;
            float2 x0 = *(const float2*)&As[kk + tg][m0 + g * 2];
            float2 x1 = *(const float2*)&As[kk + tg + 4][m0 + g * 2];
            uint32_t a0 = __float_as_uint(x0.x), a1 = __float_as_uint(x0.y);
            uint32_t a2 = __float_as_uint(x1.x), a3 = __float_as_uint(x1.y);
            float4 b0lo = *(const float4*)&Bs[kk + tg][g * 8];
            float4 b0hi = *(const float4*)&Bs[kk + tg][g * 8 + 4];
            float4 b1lo = *(const float4*)&Bs[kk + tg + 4][g * 8];
            float4 b1hi = *(const float4*)&Bs[kk + tg + 4][g * 8 + 4];
            float bf0[8] = {b0lo.x, b0lo.y, b0lo.z, b0lo.w, b0hi.x, b0hi.y, b0hi.z, b0hi.w};
            float bf1[8] = {b1lo.x, b1lo.y, b1lo.z, b1lo.w, b1hi.x, b1hi.y, b1hi.z, b1hi.w};
#pragma unroll
            for (int nt = 0; nt < 8; nt++) {
                asm volatile(
                    "mma.sync.aligned.m16n8k8.row.col.f32.tf32.tf32.f32 "
                    "{%0,%1,%2,%3}, {%4,%5,%6,%7}, {%8,%9}, {%0,%1,%2,%3};"
                    : "+f"(acc[nt][0]), "+f"(acc[nt][1]), "+f"(acc[nt][2]), "+f"(acc[nt][3])
                    : "r"(a0), "r"(a1), "r"(a2), "r"(a3),
                      "r"(__float_as_uint(bf0[nt])), "r"(__float_as_uint(bf1[nt])));
            }
        }
        __syncthreads();
    }

#pragma unroll
    for (int nt = 0; nt < 8; nt++) {
#pragma unroll
        for (int hh = 0; hh < 2; hh++) {
            int q = q0 + m0 + g + hh * 8;
#pragma unroll
            for (int j = 0; j < 2; j++) {
                int d = nt * 8 + 2 * tg + j;
                O[((size_t)(b * NS + q)) * ND + h * NDH + d] = acc[nt][hh * 2 + j];
            }
        }
    }
}

// ---------------- loss -------------------------------------------------------
__global__ __launch_bounds__(512) void loss_row_k(const float* __restrict__ logits,
                                                  const int* __restrict__ idx,
                                                  const int* __restrict__ mask,
                                                  float* __restrict__ nll) {
    int row = blockIdx.x;
    int b = row / NS, s = row % NS;
    const float* lr = logits + (size_t)row * NV;
    int tid = threadIdx.x;
    __shared__ float red[512];
    float mx = -3.4e38f;
    for (int i = tid; i < NV; i += 512) mx = fmaxf(mx, lr[i]);
    red[tid] = mx; __syncthreads();
    for (int o = 256; o > 0; o >>= 1) { if (tid < o) red[tid] = fmaxf(red[tid], red[tid + o]); __syncthreads(); }
    mx = red[0]; __syncthreads();
    float sum = 0.f;
    for (int i = tid; i < NV; i += 512) sum += __expf(lr[i] - mx);
    red[tid] = sum; __syncthreads();
    for (int o = 256; o > 0; o >>= 1) { if (tid < o) red[tid] += red[tid + o]; __syncthreads(); }
    if (tid == 0) {
        int tgt = idx[b * (NS + 1) + s + 1];
        float lse = mx + logf(red[0]);
        nll[row] = (lse - lr[tgt]) * (float)mask[row];
    }
}

__global__ __launch_bounds__(1024) void loss_final_k(const float* __restrict__ nll,
                                                     float* __restrict__ out) {
    __shared__ float red[1024];
    int tid = threadIdx.x;
    red[tid] = nll[tid] + nll[tid + 1024];
    __syncthreads();
    for (int o = 512; o > 0; o >>= 1) { if (tid < o) red[tid] += red[tid + o]; __syncthreads(); }
    if (tid == 0) out[0] = red[0] * (1.0f / (float)NBS);
}

// ---------------- host orchestration -----------------------------------------
extern "C" void kernel_launch(void* const* d_in, const int* in_sizes, int n_in,
                              void* d_out, int out_size) {
    const int*   idx  = (const int*)d_in[0];
    const int*   mask = (const int*)d_in[1];
    const float* tok  = (const float*)d_in[2];
    const float* pos  = (const float*)d_in[3];
    const float* Wq   = (const float*)d_in[4];
    const float* bq   = (const float*)d_in[5];
    const float* Wk   = (const float*)d_in[6];
    const float* bk   = (const float*)d_in[7];
    const float* Wv   = (const float*)d_in[8];
    const float* bv   = (const float*)d_in[9];
    const float* Wo   = (const float*)d_in[10];
    const float* bo   = (const float*)d_in[11];
    const float* ln1g = (const float*)d_in[12];
    const float* ln1b = (const float*)d_in[13];
    const float* W1   = (const float*)d_in[14];
    const float* b1   = (const float*)d_in[15];
    const float* W2   = (const float*)d_in[16];
    const float* b2   = (const float*)d_in[17];
    const float* ln2g = (const float*)d_in[18];
    const float* ln2b = (const float*)d_in[19];
    const float* lnfg = (const float*)d_in[20];
    const float* lnfb = (const float*)d_in[21];
    const float* headw= (const float*)d_in[22];
    float* out = (float*)d_out;

    float *x, *h, *q, *k, *v, *o, *ff, *att, *nll;
    cudaGetSymbolAddress((void**)&x,   g_x);
    cudaGetSymbolAddress((void**)&h,   g_h);
    cudaGetSymbolAddress((void**)&q,   g_q);
    cudaGetSymbolAddress((void**)&k,   g_k);
    cudaGetSymbolAddress((void**)&v,   g_v);
    cudaGetSymbolAddress((void**)&o,   g_o);
    cudaGetSymbolAddress((void**)&ff,  g_ff);
    cudaGetSymbolAddress((void**)&att, g_att);
    cudaGetSymbolAddress((void**)&nll, g_nll);

    embed_k<<<NBS, 256>>>(idx, mask, tok, pos, x);

    dim3 gQKV(ND / 64, NBS / 128, 3);   // 384 CTAs
    dim3 gDD(ND / 64, NBS / 128);       // 128 CTAs
    dim3 gDF(NFF / 128, NBS / 128);     // 256 CTAs
    dim3 gQK(136, NB * NH);             // lower-triangular 64x64 tiles
    dim3 gAV(NS / 64, NB * NH);         // 256 CTAs

    for (int l = 0; l < NL; l++) {
        const float* wq = Wq + (size_t)l * ND * ND;
        const float* wk = Wk + (size_t)l * ND * ND;
        const float* wv = Wv + (size_t)l * ND * ND;
        const float* wo = Wo + (size_t)l * ND * ND;
        const float* w1 = W1 + (size_t)l * ND * NFF;
        const float* w2 = W2 + (size_t)l * NFF * ND;

        ln_k<<<NBS, 256>>>(x, ln1g + l * ND, ln1b + l * ND, h);
        TriPtrs t;
        t.w[0] = wq; t.w[1] = wk; t.w[2] = wv;
        t.b[0] = bq + l * ND; t.b[1] = bk + l * ND; t.b[2] = bv + l * ND;
        t.c[0] = q; t.c[1] = k; t.c[2] = v;
        gemm_qkv<<<gQKV, 256>>>(h, t, NBS, ND, ND);
        qk_mma<<<gQK, 128>>>(q, k, att);
        softmax_k<<<NB * NH * NS, 256>>>(att);
        av_mma<<<gAV, 128>>>(att, v, o);
        gemm_tc<0, true, true, 64, true><<<gDD, 256>>>(o, wo, bo + l * ND, x, x, NBS, ND, ND);
        ln_k<<<NBS, 256>>>(x, ln2g + l * ND, ln2b + l * ND, h);
        gemm_tc<1, true, false, 128, true><<<gDF, 256>>>(h, w1, b1 + l * NFF, nullptr, ff, NBS, NFF, ND);
        gemm_tc<0, true, true, 64, true><<<gDD, 256>>>(ff, w2, b2 + l * ND, x, x, NBS, ND, NFF);
    }

    ln_k<<<NBS, 256>>>(x, lnfg, lnfb, h);
    dim3 gHead((NV + 127) / 128, NBS / 128);
    gemm_tc<0, false, false, 128, false><<<gHead, 256>>>(h, headw, nullptr, nullptr, out, NBS, NV, ND);

    loss_row_k<<<NBS, 512>>>(out, idx, mask, nll);
    loss_final_k<<<1, 1024>>>(nll, out + (size_t)NBS * NV);
}

// round 10
// speedup vs baseline: 1.9410x; 1.0477x over previous
#include <cuda_runtime.h>
#include <cuda_bf16.h>
#include <math.h>
#include <stdint.h>

// Problem dims
constexpr int NB  = 2;
constexpr int NS  = 1024;
constexpr int ND  = 512;
constexpr int NH  = 8;
constexpr int NDH = 64;
constexpr int NL  = 6;
constexpr int NV  = 50257;
constexpr int NBS = NB * NS;      // 2048
constexpr int NFF = 4 * ND;       // 2048
constexpr float INV_SCALE = 0.04419417382415922f; // 1/sqrt(512)

// ---------------- scratch (static device globals; no allocation) -------------
__device__ float g_x[NBS * ND];
__device__ float g_h[NBS * ND];
__device__ float g_q[NBS * ND];
__device__ float g_k[NBS * ND];
__device__ float g_v[NBS * ND];
__device__ float g_o[NBS * ND];
__device__ float g_ff[NBS * NFF];
__device__ float g_att[(size_t)NB * NH * NS * NS];   // 64 MB (raw scores)
__device__ float g_nll[NBS];

__device__ __forceinline__ float to_tf32(float x) {
    uint32_t u;
    asm("cvt.rna.tf32.f32 %0, %1;" : "=r"(u) : "f"(x));
    return __uint_as_float(u);
}

// Fragment-friendly column permutations.
__device__ __forceinline__ int ac16(int m) {
    return (m & ~15) | ((m & 7) << 1) | ((m >> 3) & 1);
}
__device__ __forceinline__ int bc32(int n) {
    return (n & ~31) | ((n & 7) << 2) | ((n >> 3) & 3);
}
__device__ __forceinline__ int bc64p(int n) {
    return ((n & 7) << 3) | ((n >> 3) & 7);
}

// ---------------- embedding --------------------------------------------------
__global__ void embed_k(const int* __restrict__ idx, const int* __restrict__ mask,
                        const float* __restrict__ tok, const float* __restrict__ pos,
                        float* __restrict__ x) {
    int row = blockIdx.x;
    int b = row / NS, s = row % NS;
    int t = idx[b * (NS + 1) + s];
    float m = (float)mask[row];
    const float* tr = tok + (size_t)t * ND;
    const float* pr = pos + (size_t)s * ND;
    float* xr = x + (size_t)row * ND;
    for (int d = threadIdx.x; d < ND; d += blockDim.x)
        xr[d] = (tr[d] + pr[d]) * m;
}

// ---------------- layernorm --------------------------------------------------
__global__ __launch_bounds__(256) void ln_k(const float* __restrict__ x,
                                            const float* __restrict__ g,
                                            const float* __restrict__ be,
                                            float* __restrict__ out) {
    int row = blockIdx.x;
    int tid = threadIdx.x;
    const float* xr = x + (size_t)row * ND;
    float v0 = xr[tid], v1 = xr[tid + 256];
    __shared__ float red[256];
    red[tid] = v0 + v1;
    __syncthreads();
    for (int o = 128; o > 0; o >>= 1) { if (tid < o) red[tid] += red[tid + o]; __syncthreads(); }
    float mean = red[0] * (1.0f / ND);
    __syncthreads();
    float d0 = v0 - mean, d1 = v1 - mean;
    red[tid] = d0 * d0 + d1 * d1;
    __syncthreads();
    for (int o = 128; o > 0; o >>= 1) { if (tid < o) red[tid] += red[tid + o]; __syncthreads(); }
    float inv = rsqrtf(red[0] * (1.0f / ND) + 1e-5f);
    float* orow = out + (size_t)row * ND;
    orow[tid]       = d0 * inv * g[tid]       + be[tid];
    orow[tid + 256] = d1 * inv * g[tid + 256] + be[tid + 256];
}

// ---------------- TF32 tensor-core GEMM, double-buffered, vectorized frags ---
template <int ACT, bool HAS_BIAS, bool HAS_RES, int BN, bool BALIGN>
__device__ __forceinline__ void gemm_body(const float* __restrict__ A,
                                          const float* __restrict__ Bm,
                                          const float* __restrict__ bias,
                                          const float* __restrict__ Res,
                                          float* __restrict__ C,
                                          int M, int N, int K,
                                          int m0, int n0) {
    constexpr int BM = 128, BK = 16;
    constexpr int WARPS_N = (BN == 128) ? 4 : 2;
    constexpr int WARPS_M = 8 / WARPS_N;
    constexpr int WM = BM / WARPS_M;
    constexpr int WN = BN / WARPS_N;
    constexpr int MT = WM / 16;
    constexpr int NT = WN / 8;
    constexpr int AP = BM + 8;
    constexpr int BP = BN + 8;

    __shared__ float As[2][BK][AP];
    __shared__ float Bs[2][BK][BP];

    int tid = threadIdx.x;
    int warp = tid >> 5;
    int lane = tid & 31;
    int g  = lane >> 2;
    int tg = lane & 3;
    int warpM = warp % WARPS_M;
    int warpN = warp / WARPS_M;

    float acc[MT][NT][4];
#pragma unroll
    for (int i = 0; i < MT; i++)
#pragma unroll
        for (int j = 0; j < NT; j++)
#pragma unroll
            for (int c = 0; c < 4; c++) acc[i][j][c] = 0.f;

    int arow = tid >> 1, ak = (tid & 1) * 8;
    int acol = ac16(arow);
    int br128 = tid >> 5, bc128 = (tid & 31) * 4;
    int br64  = tid >> 4, bc64  = (tid & 15) * 4;

    float4 ra0, ra1, rb0, rb1;

    auto loadA = [&](int k0) {
        const float* ap = A + (size_t)(m0 + arow) * K + k0 + ak;
        ra0 = *(const float4*)ap;
        ra1 = *(const float4*)(ap + 4);
    };
    auto loadB = [&](int k0) {
        if (BN == 128) {
            if (BALIGN) {
                rb0 = *(const float4*)(Bm + (size_t)(k0 + br128) * N + n0 + bc128);
                rb1 = *(const float4*)(Bm + (size_t)(k0 + br128 + 8) * N + n0 + bc128);
            } else {
                const float* bp0 = Bm + (size_t)(k0 + br128) * N;
                const float* bp1 = Bm + (size_t)(k0 + br128 + 8) * N;
                int c0 = n0 + bc128;
                rb0.x = (c0 + 0 < N) ? bp0[c0 + 0] : 0.f;
                rb0.y = (c0 + 1 < N) ? bp0[c0 + 1] : 0.f;
                rb0.z = (c0 + 2 < N) ? bp0[c0 + 2] : 0.f;
                rb0.w = (c0 + 3 < N) ? bp0[c0 + 3] : 0.f;
                rb1.x = (c0 + 0 < N) ? bp1[c0 + 0] : 0.f;
                rb1.y = (c0 + 1 < N) ? bp1[c0 + 1] : 0.f;
                rb1.z = (c0 + 2 < N) ? bp1[c0 + 2] : 0.f;
                rb1.w = (c0 + 3 < N) ? bp1[c0 + 3] : 0.f;
            }
        } else {
            rb0 = *(const float4*)(Bm + (size_t)(k0 + br64) * N + n0 + bc64);
        }
    };
    auto storeA = [&](int s) {
        As[s][ak + 0][acol] = to_tf32(ra0.x); As[s][ak + 1][acol] = to_tf32(ra0.y);
        As[s][ak + 2][acol] = to_tf32(ra0.z); As[s][ak + 3][acol] = to_tf32(ra0.w);
        As[s][ak + 4][acol] = to_tf32(ra1.x); As[s][ak + 5][acol] = to_tf32(ra1.y);
        As[s][ak + 6][acol] = to_tf32(ra1.z); As[s][ak + 7][acol] = to_tf32(ra1.w);
    };
    auto storeB = [&](int s) {
        if (BN == 128) {
            Bs[s][br128][bc32(bc128 + 0)] = to_tf32(rb0.x);
            Bs[s][br128][bc32(bc128 + 1)] = to_tf32(rb0.y);
            Bs[s][br128][bc32(bc128 + 2)] = to_tf32(rb0.z);
            Bs[s][br128][bc32(bc128 + 3)] = to_tf32(rb0.w);
            Bs[s][br128 + 8][bc32(bc128 + 0)] = to_tf32(rb1.x);
            Bs[s][br128 + 8][bc32(bc128 + 1)] = to_tf32(rb1.y);
            Bs[s][br128 + 8][bc32(bc128 + 2)] = to_tf32(rb1.z);
            Bs[s][br128 + 8][bc32(bc128 + 3)] = to_tf32(rb1.w);
        } else {
            Bs[s][br64][bc32(bc64 + 0)] = to_tf32(rb0.x);
            Bs[s][br64][bc32(bc64 + 1)] = to_tf32(rb0.y);
            Bs[s][br64][bc32(bc64 + 2)] = to_tf32(rb0.z);
            Bs[s][br64][bc32(bc64 + 3)] = to_tf32(rb0.w);
        }
    };

    int nTiles = K / BK;
    loadA(0); loadB(0);
    storeA(0); storeB(0);
    __syncthreads();

    for (int t = 0; t < nTiles; t++) {
        int cur = t & 1, nxt = cur ^ 1;
        bool more = (t + 1 < nTiles);
        if (more) { loadA((t + 1) * BK); loadB((t + 1) * BK); }

#pragma unroll
        for (int kk = 0; kk < BK; kk += 8) {
            uint32_t afr[MT][4];
            float bfr0[NT], bfr1[NT];
#pragma unroll
            for (int mt = 0; mt < MT; mt++) {
                int mc = warpM * WM + mt * 16 + g * 2;
                float2 x0 = *(const float2*)&As[cur][kk + tg][mc];
                float2 x1 = *(const float2*)&As[cur][kk + tg + 4][mc];
                afr[mt][0] = __float_as_uint(x0.x);
                afr[mt][1] = __float_as_uint(x0.y);
                afr[mt][2] = __float_as_uint(x1.x);
                afr[mt][3] = __float_as_uint(x1.y);
            }
            {
                int nc = warpN * WN + g * 4;
                float4 b0 = *(const float4*)&Bs[cur][kk + tg][nc];
                float4 b1 = *(const float4*)&Bs[cur][kk + tg + 4][nc];
                bfr0[0] = b0.x; bfr0[1] = b0.y; bfr0[2] = b0.z; bfr0[3] = b0.w;
                bfr1[0] = b1.x; bfr1[1] = b1.y; bfr1[2] = b1.z; bfr1[3] = b1.w;
            }
#pragma unroll
            for (int mt = 0; mt < MT; mt++)
#pragma unroll
                for (int nt = 0; nt < NT; nt++) {
                    asm volatile(
                        "mma.sync.aligned.m16n8k8.row.col.f32.tf32.tf32.f32 "
                        "{%0,%1,%2,%3}, {%4,%5,%6,%7}, {%8,%9}, {%0,%1,%2,%3};"
                        : "+f"(acc[mt][nt][0]), "+f"(acc[mt][nt][1]),
                          "+f"(acc[mt][nt][2]), "+f"(acc[mt][nt][3])
                        : "r"(afr[mt][0]), "r"(afr[mt][1]),
                          "r"(afr[mt][2]), "r"(afr[mt][3]),
                          "r"(__float_as_uint(bfr0[nt])), "r"(__float_as_uint(bfr1[nt])));
                }
        }
        if (more) { storeA(nxt); storeB(nxt); }
        __syncthreads();
    }

#pragma unroll
    for (int mt = 0; mt < MT; mt++) {
#pragma unroll
        for (int nt = 0; nt < NT; nt++) {
            int row0 = m0 + warpM * WM + mt * 16 + g;
            int col0 = n0 + warpN * WN + nt * 8 + 2 * tg;
#pragma unroll
            for (int hh = 0; hh < 2; hh++) {
                int row = row0 + hh * 8;
#pragma unroll
                for (int j = 0; j < 2; j++) {
                    int col = col0 + j;
                    if (col < N) {
                        float v = acc[mt][nt][hh * 2 + j];
                        if (HAS_BIAS) v += bias[col];
                        if (ACT == 1) v = 0.5f * v * (1.0f + erff(v * 0.70710678118654752f));
                        if (HAS_RES) v += Res[(size_t)row * N + col];
                        C[(size_t)row * N + col] = v;
                    }
                }
            }
        }
    }
}

template <int ACT, bool HAS_BIAS, bool HAS_RES, int BN, bool BALIGN>
__global__ __launch_bounds__(256) void gemm_tc(const float* __restrict__ A,
                                               const float* __restrict__ Bm,
                                               const float* __restrict__ bias,
                                               const float* __restrict__ Res,
                                               float* __restrict__ C,
                                               int M, int N, int K) {
    gemm_body<ACT, HAS_BIAS, HAS_RES, BN, BALIGN>(
        A, Bm, bias, Res, C, M, N, K, blockIdx.y * 128, blockIdx.x * BN);
}

struct TriPtrs {
    const float* w[3];
    const float* b[3];
    float*       c[3];
};
__global__ __launch_bounds__(256) void gemm_qkv(const float* __restrict__ A,
                                                TriPtrs t, int M, int N, int K) {
    int z = blockIdx.z;
    gemm_body<0, true, false, 64, true>(
        A, t.w[z], t.b[z], nullptr, t.c[z], M, N, K, blockIdx.y * 128, blockIdx.x * 64);
}

// ---------------- QK^T via mma: 64x64 tiles, lower-triangular only -----------
// Writes scaled scores; -inf above diagonal (within diagonal tiles).
__global__ __launch_bounds__(128) void qk_mma(const float* __restrict__ Q,
                                              const float* __restrict__ Kg,
                                              float* __restrict__ Att) {
    __shared__ float As[NDH][72];
    __shared__ float Bs[NDH][72];

    int i = blockIdx.x;
    int qt = (int)((sqrtf(8.f * i + 1.f) - 1.f) * 0.5f);
    while ((qt + 1) * (qt + 2) / 2 <= i) qt++;
    while (qt * (qt + 1) / 2 > i) qt--;
    int kt = i - qt * (qt + 1) / 2;
    int q0 = qt * 64, k0 = kt * 64;
    int bh = blockIdx.y;
    int b = bh >> 3, h = bh & 7;

    int tid = threadIdx.x;
    int row = tid >> 1;
    int koff = (tid & 1) * 32;
    int acol = ac16(row);
    int bcol = bc64p(row);

    {
        const float* qp = Q + ((size_t)(b * NS + q0 + row)) * ND + h * NDH + koff;
        const float* kp = Kg + ((size_t)(b * NS + k0 + row)) * ND + h * NDH + koff;
#pragma unroll
        for (int j = 0; j < 8; j++) {
            float4 f = *(const float4*)(qp + j * 4);
            As[koff + j * 4 + 0][acol] = to_tf32(f.x);
            As[koff + j * 4 + 1][acol] = to_tf32(f.y);
            As[koff + j * 4 + 2][acol] = to_tf32(f.z);
            As[koff + j * 4 + 3][acol] = to_tf32(f.w);
            float4 g4 = *(const float4*)(kp + j * 4);
            Bs[koff + j * 4 + 0][bcol] = to_tf32(g4.x);
            Bs[koff + j * 4 + 1][bcol] = to_tf32(g4.y);
            Bs[koff + j * 4 + 2][bcol] = to_tf32(g4.z);
            Bs[koff + j * 4 + 3][bcol] = to_tf32(g4.w);
        }
    }
    __syncthreads();

    int warp = tid >> 5;
    int lane = tid & 31;
    int g = lane >> 2, tg = lane & 3;
    int m0 = warp * 16;

    float acc[8][4];
#pragma unroll
    for (int nt = 0; nt < 8; nt++)
#pragma unroll
        for (int c = 0; c < 4; c++) acc[nt][c] = 0.f;

#pragma unroll
    for (int ks = 0; ks < 8; ks++) {
        int kk = ks * 8;
        float2 x0 = *(const float2*)&As[kk + tg][m0 + g * 2];
        float2 x1 = *(const float2*)&As[kk + tg + 4][m0 + g * 2];
        uint32_t a0 = __float_as_uint(x0.x), a1 = __float_as_uint(x0.y);
        uint32_t a2 = __float_as_uint(x1.x), a3 = __float_as_uint(x1.y);
        float4 b0lo = *(const float4*)&Bs[kk + tg][g * 8];
        float4 b0hi = *(const float4*)&Bs[kk + tg][g * 8 + 4];
        float4 b1lo = *(const float4*)&Bs[kk + tg + 4][g * 8];
        float4 b1hi = *(const float4*)&Bs[kk + tg + 4][g * 8 + 4];
        float bf0[8] = {b0lo.x, b0lo.y, b0lo.z, b0lo.w, b0hi.x, b0hi.y, b0hi.z, b0hi.w};
        float bf1[8] = {b1lo.x, b1lo.y, b1lo.z, b1lo.w, b1hi.x, b1hi.y, b1hi.z, b1hi.w};
#pragma unroll
        for (int nt = 0; nt < 8; nt++) {
            asm volatile(
                "mma.sync.aligned.m16n8k8.row.col.f32.tf32.tf32.f32 "
                "{%0,%1,%2,%3}, {%4,%5,%6,%7}, {%8,%9}, {%0,%1,%2,%3};"
                : "+f"(acc[nt][0]), "+f"(acc[nt][1]), "+f"(acc[nt][2]), "+f"(acc[nt][3])
                : "r"(a0), "r"(a1), "r"(a2), "r"(a3),
                  "r"(__float_as_uint(bf0[nt])), "r"(__float_as_uint(bf1[nt])));
        }
    }

#pragma unroll
    for (int nt = 0; nt < 8; nt++) {
#pragma unroll
        for (int hh = 0; hh < 2; hh++) {
            int q = q0 + m0 + g + hh * 8;
#pragma unroll
            for (int j = 0; j < 2; j++) {
                int k = k0 + nt * 8 + 2 * tg + j;
                float v = (k <= q) ? acc[nt][hh * 2 + j] * INV_SCALE : -INFINITY;
                Att[((size_t)bh * NS + q) * NS + k] = v;
            }
        }
    }
}

// ---------------- fused online-softmax + P@V via mma -------------------------
// grid (NS/64, NB*NH), 128 threads. Tile: 64 q-rows x 64 dims, kc step 32.
// Threads 0..63: online softmax for row t + permuted P staging.
// Threads 64..127: V tile staging. Then all warps run the mma.
__global__ __launch_bounds__(128) void av_flash(const float* __restrict__ Att,
                                                const float* __restrict__ Vg,
                                                float* __restrict__ O) {
    __shared__ float As[32][72];   // [k][ac16(q_row)] exp(S) tile
    __shared__ float Bs[32][72];   // [k][bc64p(d)] V tile
    __shared__ float fac_s[64];
    __shared__ float l_s[64];

    int q0 = (gridDim.x - 1 - blockIdx.x) * 64;   // longest first
    int bh = blockIdx.y;
    int b = bh >> 3, h = bh & 7;
    int tid = threadIdx.x;

    const float* abase = Att + (size_t)bh * NS * NS;
    const float* vbase = Vg + (size_t)b * NS * ND + h * NDH;

    int warp = tid >> 5;
    int lane = tid & 31;
    int g = lane >> 2, tg = lane & 3;
    int m0 = warp * 16;

    float acc[8][4];
#pragma unroll
    for (int nt = 0; nt < 8; nt++)
#pragma unroll
        for (int c = 0; c < 4; c++) acc[nt][c] = 0.f;

    float m_old = -INFINITY, l = 0.f;     // owners: tid < 64
    int pac = ac16(tid & 63);

    for (int kc = 0; kc < q0 + 64; kc += 32) {
        if (tid < 64) {
            const float* sp = abase + (size_t)(q0 + tid) * NS + kc;
            float sv[32];
#pragma unroll
            for (int j = 0; j < 8; j++) {
                float4 f = *(const float4*)(sp + j * 4);
                sv[j * 4 + 0] = f.x; sv[j * 4 + 1] = f.y;
                sv[j * 4 + 2] = f.z; sv[j * 4 + 3] = f.w;
            }
            float mb = sv[0];
#pragma unroll
            for (int j = 1; j < 32; j++) mb = fmaxf(mb, sv[j]);
            float mn = fmaxf(m_old, mb);
            float fc = __expf(m_old - mn);
            float ps = 0.f;
#pragma unroll
            for (int j = 0; j < 32; j++) {
                float e = __expf(sv[j] - mn);
                ps += e;
                As[j][pac] = to_tf32(e);
            }
            l = l * fc + ps;
            m_old = mn;
            fac_s[tid] = fc;
        } else {
            int u = tid - 64;
            int vr = u >> 1;             // 0..31
            int vc = (u & 1) * 32;
            const float* vp = vbase + (size_t)(kc + vr) * ND + vc;
#pragma unroll
            for (int j = 0; j < 8; j++) {
                float4 f = *(const float4*)(vp + j * 4);
                Bs[vr][bc64p(vc + j * 4 + 0)] = to_tf32(f.x);
                Bs[vr][bc64p(vc + j * 4 + 1)] = to_tf32(f.y);
                Bs[vr][bc64p(vc + j * 4 + 2)] = to_tf32(f.z);
                Bs[vr][bc64p(vc + j * 4 + 3)] = to_tf32(f.w);
            }
        }
        __syncthreads();

        float f1 = fac_s[m0 + g];
        float f2 = fac_s[m0 + g + 8];
#pragma unroll
        for (int nt = 0; nt < 8; nt++) {
            acc[nt][0] *= f1; acc[nt][1] *= f1;
            acc[nt][2] *= f2; acc[nt][3] *= f2;
        }

#pragma unroll
        for (int ks = 0; ks < 4; ks++) {
            int kk = ks * 8;
            float2 x0 = *(const float2*)&As[kk + tg][m0 + g * 2];
            float2 x1 = *(const float2*)&As[kk + tg + 4][m0 + g * 2];
            uint32_t a0 = __float_as_uint(x0.x), a1 = __float_as_uint(x0.y);
            uint32_t a2 = __float_as_uint(x1.x), a3 = __float_as_uint(x1.y);
            float4 b0lo = *(const float4*)&Bs[kk + tg][g * 8];
            float4 b0hi = *(const float4*)&Bs[kk + tg][g * 8 + 4];
            float4 b1lo = *(const float4*)&Bs[kk + tg + 4][g * 8];
            float4 b1hi = *(const float4*)&Bs[kk + tg + 4][g * 8 + 4];
            float bf0[8] = {b0lo.x, b0lo.y, b0lo.z, b0lo.w, b0hi.x, b0hi.y, b0hi.z, b0hi.w};
            float bf1[8] = {b1lo.x, b1lo.y, b1lo.z, b1lo.w, b1hi.x, b1hi.y, b1hi.z, b1hi.w};
#pragma unroll
            for (int nt = 0; nt < 8; nt++) {
                asm volatile(
                    "mma.sync.aligned.m16n8k8.row.col.f32.tf32.tf32.f32 "
                    "{%0,%1,%2,%3}, {%4,%5,%6,%7}, {%8,%9}, {%0,%1,%2,%3};"
                    : "+f"(acc[nt][0]), "+f"(acc[nt][1]), "+f"(acc[nt][2]), "+f"(acc[nt][3])
                    : "r"(a0), "r"(a1), "r"(a2), "r"(a3),
                      "r"(__float_as_uint(bf0[nt])), "r"(__float_as_uint(bf1[nt])));
            }
        }
        __syncthreads();
    }

    if (tid < 64) l_s[tid] = l;
    __syncthreads();
    float i1 = 1.0f / l_s[m0 + g];
    float i2 = 1.0f / l_s[m0 + g + 8];

#pragma unroll
    for (int nt = 0; nt < 8; nt++) {
#pragma unroll
        for (int hh = 0; hh < 2; hh++) {
            int q = q0 + m0 + g + hh * 8;
            float inv = hh ? i2 : i1;
#pragma unroll
            for (int j = 0; j < 2; j++) {
                int d = nt * 8 + 2 * tg + j;
                O[((size_t)(b * NS + q)) * ND + h * NDH + d] = acc[nt][hh * 2 + j] * inv;
            }
        }
    }
}

// ---------------- loss: single-pass online logsumexp -------------------------
__global__ __launch_bounds__(512) void loss_row_k(const float* __restrict__ logits,
                                                  const int* __restrict__ idx,
                                                  const int* __restrict__ mask,
                                                  float* __restrict__ nll) {
    int row = blockIdx.x;
    int b = row / NS, s = row % NS;
    const float* lr = logits + (size_t)row * NV;
    int tid = threadIdx.x;
    __shared__ float redm[512];
    __shared__ float reds[512];
    float m = -INFINITY, sum = 0.f;
    for (int i = tid; i < NV; i += 512) {
        float x = lr[i];
        if (x > m) { sum = sum * __expf(m - x) + 1.f; m = x; }
        else       { sum += __expf(x - m); }
    }
    redm[tid] = m; reds[tid] = sum;
    __syncthreads();
    for (int o = 256; o > 0; o >>= 1) {
        if (tid < o) {
            float m2 = redm[tid + o], s2 = reds[tid + o];
            float m1 = redm[tid],     s1 = reds[tid];
            float M = fmaxf(m1, m2);
            redm[tid] = M;
            reds[tid] = s1 * __expf(m1 - M) + s2 * __expf(m2 - M);
        }
        __syncthreads();
    }
    if (tid == 0) {
        int tgt = idx[b * (NS + 1) + s + 1];
        float lse = redm[0] + logf(reds[0]);
        nll[row] = (lse - lr[tgt]) * (float)mask[row];
    }
}

__global__ __launch_bounds__(1024) void loss_final_k(const float* __restrict__ nll,
                                                     float* __restrict__ out) {
    __shared__ float red[1024];
    int tid = threadIdx.x;
    red[tid] = nll[tid] + nll[tid + 1024];
    __syncthreads();
    for (int o = 512; o > 0; o >>= 1) { if (tid < o) red[tid] += red[tid + o]; __syncthreads(); }
    if (tid == 0) out[0] = red[0] * (1.0f / (float)NBS);
}

// ---------------- host orchestration -----------------------------------------
extern "C" void kernel_launch(void* const* d_in, const int* in_sizes, int n_in,
                              void* d_out, int out_size) {
    const int*   idx  = (const int*)d_in[0];
    const int*   mask = (const int*)d_in[1];
    const float* tok  = (const float*)d_in[2];
    const float* pos  = (const float*)d_in[3];
    const float* Wq   = (const float*)d_in[4];
    const float* bq   = (const float*)d_in[5];
    const float* Wk   = (const float*)d_in[6];
    const float* bk   = (const float*)d_in[7];
    const float* Wv   = (const float*)d_in[8];
    const float* bv   = (const float*)d_in[9];
    const float* Wo   = (const float*)d_in[10];
    const float* bo   = (const float*)d_in[11];
    const float* ln1g = (const float*)d_in[12];
    const float* ln1b = (const float*)d_in[13];
    const float* W1   = (const float*)d_in[14];
    const float* b1   = (const float*)d_in[15];
    const float* W2   = (const float*)d_in[16];
    const float* b2   = (const float*)d_in[17];
    const float* ln2g = (const float*)d_in[18];
    const float* ln2b = (const float*)d_in[19];
    const float* lnfg = (const float*)d_in[20];
    const float* lnfb = (const float*)d_in[21];
    const float* headw= (const float*)d_in[22];
    float* out = (float*)d_out;

    float *x, *h, *q, *k, *v, *o, *ff, *att, *nll;
    cudaGetSymbolAddress((void**)&x,   g_x);
    cudaGetSymbolAddress((void**)&h,   g_h);
    cudaGetSymbolAddress((void**)&q,   g_q);
    cudaGetSymbolAddress((void**)&k,   g_k);
    cudaGetSymbolAddress((void**)&v,   g_v);
    cudaGetSymbolAddress((void**)&o,   g_o);
    cudaGetSymbolAddress((void**)&ff,  g_ff);
    cudaGetSymbolAddress((void**)&att, g_att);
    cudaGetSymbolAddress((void**)&nll, g_nll);

    embed_k<<<NBS, 256>>>(idx, mask, tok, pos, x);

    dim3 gQKV(ND / 64, NBS / 128, 3);   // 384 CTAs
    dim3 gDD(ND / 64, NBS / 128);       // 128 CTAs
    dim3 gDF(NFF / 128, NBS / 128);     // 256 CTAs
    dim3 gQK(136, NB * NH);             // lower-triangular 64x64 tiles
    dim3 gAV(NS / 64, NB * NH);         // 256 CTAs

    for (int l = 0; l < NL; l++) {
        const float* wq = Wq + (size_t)l * ND * ND;
        const float* wk = Wk + (size_t)l * ND * ND;
        const float* wv = Wv + (size_t)l * ND * ND;
        const float* wo = Wo + (size_t)l * ND * ND;
        const float* w1 = W1 + (size_t)l * ND * NFF;
        const float* w2 = W2 + (size_t)l * NFF * ND;

        ln_k<<<NBS, 256>>>(x, ln1g + l * ND, ln1b + l * ND, h);
        TriPtrs t;
        t.w[0] = wq; t.w[1] = wk; t.w[2] = wv;
        t.b[0] = bq + l * ND; t.b[1] = bk + l * ND; t.b[2] = bv + l * ND;
        t.c[0] = q; t.c[1] = k; t.c[2] = v;
        gemm_qkv<<<gQKV, 256>>>(h, t, NBS, ND, ND);
        qk_mma<<<gQK, 128>>>(q, k, att);
        av_flash<<<gAV, 128>>>(att, v, o);
        gemm_tc<0, true, true, 64, true><<<gDD, 256>>>(o, wo, bo + l * ND, x, x, NBS, ND, ND);
        ln_k<<<NBS, 256>>>(x, ln2g + l * ND, ln2b + l * ND, h);
        gemm_tc<1, true, false, 128, true><<<gDF, 256>>>(h, w1, b1 + l * NFF, nullptr, ff, NBS, NFF, ND);
        gemm_tc<0, true, true, 64, true><<<gDD, 256>>>(ff, w2, b2 + l * ND, x, x, NBS, ND, NFF);
    }

    ln_k<<<NBS, 256>>>(x, lnfg, lnfb, h);
    dim3 gHead((NV + 127) / 128, NBS / 128);
    gemm_tc<0, false, false, 128, false><<<gHead, 256>>>(h, headw, nullptr, nullptr, out, NBS, NV, ND);

    loss_row_k<<<NBS, 512>>>(out, idx, mask, nll);
    loss_final_k<<<1, 1024>>>(nll, out + (size_t)NBS * NV);
}

// round 11
// speedup vs baseline: 2.0494x; 1.0559x over previous
#include <cuda_runtime.h>
#include <cuda_bf16.h>
#include <math.h>
#include <stdint.h>

// Problem dims
constexpr int NB  = 2;
constexpr int NS  = 1024;
constexpr int ND  = 512;
constexpr int NH  = 8;
constexpr int NDH = 64;
constexpr int NL  = 6;
constexpr int NV  = 50257;
constexpr int NBS = NB * NS;      // 2048
constexpr int NFF = 4 * ND;       // 2048
constexpr float INV_SCALE = 0.04419417382415922f; // 1/sqrt(512)

// ---------------- scratch (static device globals; no allocation) -------------
__device__ float g_x[NBS * ND];
__device__ float g_h[NBS * ND];
__device__ float g_q[NBS * ND];
__device__ float g_k[NBS * ND];
__device__ float g_v[NBS * ND];
__device__ float g_o[NBS * ND];
__device__ float g_ff[NBS * NFF];
__device__ float g_nll[NBS];

__device__ __forceinline__ float to_tf32(float x) {
    uint32_t u;
    asm("cvt.rna.tf32.f32 %0, %1;" : "=r"(u) : "f"(x));
    return __uint_as_float(u);
}

// Fragment-friendly column permutations.
__device__ __forceinline__ int ac16(int m) {
    return (m & ~15) | ((m & 7) << 1) | ((m >> 3) & 1);
}
__device__ __forceinline__ int bc32(int n) {
    return (n & ~31) | ((n & 7) << 2) | ((n >> 3) & 3);
}
__device__ __forceinline__ int bc64p(int n) {
    return ((n & 7) << 3) | ((n >> 3) & 7);
}

// ---------------- embedding --------------------------------------------------
__global__ void embed_k(const int* __restrict__ idx, const int* __restrict__ mask,
                        const float* __restrict__ tok, const float* __restrict__ pos,
                        float* __restrict__ x) {
    int row = blockIdx.x;
    int b = row / NS, s = row % NS;
    int t = idx[b * (NS + 1) + s];
    float m = (float)mask[row];
    const float* tr = tok + (size_t)t * ND;
    const float* pr = pos + (size_t)s * ND;
    float* xr = x + (size_t)row * ND;
    for (int d = threadIdx.x; d < ND; d += blockDim.x)
        xr[d] = (tr[d] + pr[d]) * m;
}

// ---------------- layernorm --------------------------------------------------
__global__ __launch_bounds__(256) void ln_k(const float* __restrict__ x,
                                            const float* __restrict__ g,
                                            const float* __restrict__ be,
                                            float* __restrict__ out) {
    int row = blockIdx.x;
    int tid = threadIdx.x;
    const float* xr = x + (size_t)row * ND;
    float v0 = xr[tid], v1 = xr[tid + 256];
    __shared__ float red[256];
    red[tid] = v0 + v1;
    __syncthreads();
    for (int o = 128; o > 0; o >>= 1) { if (tid < o) red[tid] += red[tid + o]; __syncthreads(); }
    float mean = red[0] * (1.0f / ND);
    __syncthreads();
    float d0 = v0 - mean, d1 = v1 - mean;
    red[tid] = d0 * d0 + d1 * d1;
    __syncthreads();
    for (int o = 128; o > 0; o >>= 1) { if (tid < o) red[tid] += red[tid + o]; __syncthreads(); }
    float inv = rsqrtf(red[0] * (1.0f / ND) + 1e-5f);
    float* orow = out + (size_t)row * ND;
    orow[tid]       = d0 * inv * g[tid]       + be[tid];
    orow[tid + 256] = d1 * inv * g[tid + 256] + be[tid + 256];
}

// ---------------- TF32 tensor-core GEMM, double-buffered, vectorized frags ---
template <int ACT, bool HAS_BIAS, bool HAS_RES, int BN, bool BALIGN>
__device__ __forceinline__ void gemm_body(const float* __restrict__ A,
                                          const float* __restrict__ Bm,
                                          const float* __restrict__ bias,
                                          const float* __restrict__ Res,
                                          float* __restrict__ C,
                                          int M, int N, int K,
                                          int m0, int n0) {
    constexpr int BM = 128, BK = 16;
    constexpr int WARPS_N = (BN == 128) ? 4 : 2;
    constexpr int WARPS_M = 8 / WARPS_N;
    constexpr int WM = BM / WARPS_M;
    constexpr int WN = BN / WARPS_N;
    constexpr int MT = WM / 16;
    constexpr int NT = WN / 8;
    constexpr int AP = BM + 8;
    constexpr int BP = BN + 8;

    __shared__ float As[2][BK][AP];
    __shared__ float Bs[2][BK][BP];

    int tid = threadIdx.x;
    int warp = tid >> 5;
    int lane = tid & 31;
    int g  = lane >> 2;
    int tg = lane & 3;
    int warpM = warp % WARPS_M;
    int warpN = warp / WARPS_M;

    float acc[MT][NT][4];
#pragma unroll
    for (int i = 0; i < MT; i++)
#pragma unroll
        for (int j = 0; j < NT; j++)
#pragma unroll
            for (int c = 0; c < 4; c++) acc[i][j][c] = 0.f;

    int arow = tid >> 1, ak = (tid & 1) * 8;
    int acol = ac16(arow);
    int br128 = tid >> 5, bc128 = (tid & 31) * 4;
    int br64  = tid >> 4, bc64  = (tid & 15) * 4;

    float4 ra0, ra1, rb0, rb1;

    auto loadA = [&](int k0) {
        const float* ap = A + (size_t)(m0 + arow) * K + k0 + ak;
        ra0 = *(const float4*)ap;
        ra1 = *(const float4*)(ap + 4);
    };
    auto loadB = [&](int k0) {
        if (BN == 128) {
            if (BALIGN) {
                rb0 = *(const float4*)(Bm + (size_t)(k0 + br128) * N + n0 + bc128);
                rb1 = *(const float4*)(Bm + (size_t)(k0 + br128 + 8) * N + n0 + bc128);
            } else {
                const float* bp0 = Bm + (size_t)(k0 + br128) * N;
                const float* bp1 = Bm + (size_t)(k0 + br128 + 8) * N;
                int c0 = n0 + bc128;
                rb0.x = (c0 + 0 < N) ? bp0[c0 + 0] : 0.f;
                rb0.y = (c0 + 1 < N) ? bp0[c0 + 1] : 0.f;
                rb0.z = (c0 + 2 < N) ? bp0[c0 + 2] : 0.f;
                rb0.w = (c0 + 3 < N) ? bp0[c0 + 3] : 0.f;
                rb1.x = (c0 + 0 < N) ? bp1[c0 + 0] : 0.f;
                rb1.y = (c0 + 1 < N) ? bp1[c0 + 1] : 0.f;
                rb1.z = (c0 + 2 < N) ? bp1[c0 + 2] : 0.f;
                rb1.w = (c0 + 3 < N) ? bp1[c0 + 3] : 0.f;
            }
        } else {
            rb0 = *(const float4*)(Bm + (size_t)(k0 + br64) * N + n0 + bc64);
        }
    };
    auto storeA = [&](int s) {
        As[s][ak + 0][acol] = to_tf32(ra0.x); As[s][ak + 1][acol] = to_tf32(ra0.y);
        As[s][ak + 2][acol] = to_tf32(ra0.z); As[s][ak + 3][acol] = to_tf32(ra0.w);
        As[s][ak + 4][acol] = to_tf32(ra1.x); As[s][ak + 5][acol] = to_tf32(ra1.y);
        As[s][ak + 6][acol] = to_tf32(ra1.z); As[s][ak + 7][acol] = to_tf32(ra1.w);
    };
    auto storeB = [&](int s) {
        if (BN == 128) {
            Bs[s][br128][bc32(bc128 + 0)] = to_tf32(rb0.x);
            Bs[s][br128][bc32(bc128 + 1)] = to_tf32(rb0.y);
            Bs[s][br128][bc32(bc128 + 2)] = to_tf32(rb0.z);
            Bs[s][br128][bc32(bc128 + 3)] = to_tf32(rb0.w);
            Bs[s][br128 + 8][bc32(bc128 + 0)] = to_tf32(rb1.x);
            Bs[s][br128 + 8][bc32(bc128 + 1)] = to_tf32(rb1.y);
            Bs[s][br128 + 8][bc32(bc128 + 2)] = to_tf32(rb1.z);
            Bs[s][br128 + 8][bc32(bc128 + 3)] = to_tf32(rb1.w);
        } else {
            Bs[s][br64][bc32(bc64 + 0)] = to_tf32(rb0.x);
            Bs[s][br64][bc32(bc64 + 1)] = to_tf32(rb0.y);
            Bs[s][br64][bc32(bc64 + 2)] = to_tf32(rb0.z);
            Bs[s][br64][bc32(bc64 + 3)] = to_tf32(rb0.w);
        }
    };

    int nTiles = K / BK;
    loadA(0); loadB(0);
    storeA(0); storeB(0);
    __syncthreads();

    for (int t = 0; t < nTiles; t++) {
        int cur = t & 1, nxt = cur ^ 1;
        bool more = (t + 1 < nTiles);
        if (more) { loadA((t + 1) * BK); loadB((t + 1) * BK); }

#pragma unroll
        for (int kk = 0; kk < BK; kk += 8) {
            uint32_t afr[MT][4];
            float bfr0[NT], bfr1[NT];
#pragma unroll
            for (int mt = 0; mt < MT; mt++) {
                int mc = warpM * WM + mt * 16 + g * 2;
                float2 x0 = *(const float2*)&As[cur][kk + tg][mc];
                float2 x1 = *(const float2*)&As[cur][kk + tg + 4][mc];
                afr[mt][0] = __float_as_uint(x0.x);
                afr[mt][1] = __float_as_uint(x0.y);
                afr[mt][2] = __float_as_uint(x1.x);
                afr[mt][3] = __float_as_uint(x1.y);
            }
            {
                int nc = warpN * WN + g * 4;
                float4 b0 = *(const float4*)&Bs[cur][kk + tg][nc];
                float4 b1 = *(const float4*)&Bs[cur][kk + tg + 4][nc];
                bfr0[0] = b0.x; bfr0[1] = b0.y; bfr0[2] = b0.z; bfr0[3] = b0.w;
                bfr1[0] = b1.x; bfr1[1] = b1.y; bfr1[2] = b1.z; bfr1[3] = b1.w;
            }
#pragma unroll
            for (int mt = 0; mt < MT; mt++)
#pragma unroll
                for (int nt = 0; nt < NT; nt++) {
                    asm volatile(
                        "mma.sync.aligned.m16n8k8.row.col.f32.tf32.tf32.f32 "
                        "{%0,%1,%2,%3}, {%4,%5,%6,%7}, {%8,%9}, {%0,%1,%2,%3};"
                        : "+f"(acc[mt][nt][0]), "+f"(acc[mt][nt][1]),
                          "+f"(acc[mt][nt][2]), "+f"(acc[mt][nt][3])
                        : "r"(afr[mt][0]), "r"(afr[mt][1]),
                          "r"(afr[mt][2]), "r"(afr[mt][3]),
                          "r"(__float_as_uint(bfr0[nt])), "r"(__float_as_uint(bfr1[nt])));
                }
        }
        if (more) { storeA(nxt); storeB(nxt); }
        __syncthreads();
    }

#pragma unroll
    for (int mt = 0; mt < MT; mt++) {
#pragma unroll
        for (int nt = 0; nt < NT; nt++) {
            int row0 = m0 + warpM * WM + mt * 16 + g;
            int col0 = n0 + warpN * WN + nt * 8 + 2 * tg;
#pragma unroll
            for (int hh = 0; hh < 2; hh++) {
                int row = row0 + hh * 8;
#pragma unroll
                for (int j = 0; j < 2; j++) {
                    int col = col0 + j;
                    if (col < N) {
                        float v = acc[mt][nt][hh * 2 + j];
                        if (HAS_BIAS) v += bias[col];
                        if (ACT == 1) v = 0.5f * v * (1.0f + erff(v * 0.70710678118654752f));
                        if (HAS_RES) v += Res[(size_t)row * N + col];
                        C[(size_t)row * N + col] = v;
                    }
                }
            }
        }
    }
}

template <int ACT, bool HAS_BIAS, bool HAS_RES, int BN, bool BALIGN, bool SWAP>
__global__ __launch_bounds__(256) void gemm_tc(const float* __restrict__ A,
                                               const float* __restrict__ Bm,
                                               const float* __restrict__ bias,
                                               const float* __restrict__ Res,
                                               float* __restrict__ C,
                                               int M, int N, int K) {
    int m0 = (SWAP ? blockIdx.x : blockIdx.y) * 128;
    int n0 = (SWAP ? blockIdx.y : blockIdx.x) * BN;
    gemm_body<ACT, HAS_BIAS, HAS_RES, BN, BALIGN>(A, Bm, bias, Res, C, M, N, K, m0, n0);
}

struct TriPtrs {
    const float* w[3];
    const float* b[3];
    float*       c[3];
};
__global__ __launch_bounds__(256) void gemm_qkv(const float* __restrict__ A,
                                                TriPtrs t, int M, int N, int K) {
    int z = blockIdx.z;
    gemm_body<0, true, false, 64, true>(
        A, t.w[z], t.b[z], nullptr, t.c[z], M, N, K, blockIdx.y * 128, blockIdx.x * 64);
}

// ---------------- fully fused flash attention (tf32 mma, online softmax) -----
// grid (NS/64, NB*NH), 128 threads (4 warps). Per CTA: 64 q-rows x full head.
// k-blocks of 32. Q staged once, frags preloaded; Q smem reused as P buffer.
__global__ __launch_bounds__(128) void attn_flash(const float* __restrict__ Q,
                                                  const float* __restrict__ Kg,
                                                  const float* __restrict__ Vg,
                                                  float* __restrict__ O) {
    __shared__ __align__(16) float Qs[NDH][72];   // [d][ac16(qrow)]; rows 0..31 reused as P
    __shared__ __align__(16) float Ks[NDH][36];   // [d][bc32(tok)]
    __shared__ __align__(16) float Vs[32][72];    // [tok][bc64p(d)]

    int q0 = (gridDim.x - 1 - blockIdx.x) * 64;   // longest first
    int bh = blockIdx.y;
    int b = bh >> 3, h = bh & 7;
    int tid = threadIdx.x;
    int warp = tid >> 5;
    int lane = tid & 31;
    int g = lane >> 2, tg = lane & 3;
    int m0 = warp * 16;

    const float* qbase = Q + (size_t)b * NS * ND + h * NDH;
    const float* kbase = Kg + (size_t)b * NS * ND + h * NDH;
    const float* vbase = Vg + (size_t)b * NS * ND + h * NDH;

    // ---- stage Q tile (64x64) ----
    {
        int row = tid >> 1;
        int doff = (tid & 1) * 32;
        int acol = ac16(row);
        const float* qp = qbase + (size_t)(q0 + row) * ND + doff;
#pragma unroll
        for (int j = 0; j < 8; j++) {
            float4 f = *(const float4*)(qp + j * 4);
            Qs[doff + j * 4 + 0][acol] = to_tf32(f.x);
            Qs[doff + j * 4 + 1][acol] = to_tf32(f.y);
            Qs[doff + j * 4 + 2][acol] = to_tf32(f.z);
            Qs[doff + j * 4 + 3][acol] = to_tf32(f.w);
        }
    }
    __syncthreads();

    // ---- preload Q fragments (8 ksteps x 4 regs) ----
    uint32_t qfr[8][4];
#pragma unroll
    for (int ks = 0; ks < 8; ks++) {
        int kk = ks * 8;
        float2 x0 = *(const float2*)&Qs[kk + tg][m0 + g * 2];
        float2 x1 = *(const float2*)&Qs[kk + tg + 4][m0 + g * 2];
        qfr[ks][0] = __float_as_uint(x0.x);
        qfr[ks][1] = __float_as_uint(x0.y);
        qfr[ks][2] = __float_as_uint(x1.x);
        qfr[ks][3] = __float_as_uint(x1.y);
    }
    float* Ps = &Qs[0][0];   // P buffer aliases Qs rows 0..31 (pitch 72)

    float Oacc[8][4];
#pragma unroll
    for (int nt = 0; nt < 8; nt++)
#pragma unroll
        for (int c = 0; c < 4; c++) Oacc[nt][c] = 0.f;

    float mo0 = -INFINITY, mo1 = -INFINITY, l0 = 0.f, l1 = 0.f;
    int qr0 = q0 + m0 + g, qr1 = qr0 + 8;
    int pc0 = m0 + 2 * g, pc1 = pc0 + 1;   // ac16(m0+g), ac16(m0+g+8)

    int nblk = (q0 + 64) >> 5;
    for (int blk = 0; blk < nblk; blk++) {
        int kc = blk << 5;
        // ---- stage K (conflict-free: lanes = 32 distinct toks) ----
        {
            int ktok = tid & 31;
            int kdoff = (tid >> 5) * 16;
            int bcol = bc32(ktok);
            const float* kp = kbase + (size_t)(kc + ktok) * ND + kdoff;
#pragma unroll
            for (int j = 0; j < 4; j++) {
                float4 f = *(const float4*)(kp + j * 4);
                Ks[kdoff + j * 4 + 0][bcol] = to_tf32(f.x);
                Ks[kdoff + j * 4 + 1][bcol] = to_tf32(f.y);
                Ks[kdoff + j * 4 + 2][bcol] = to_tf32(f.z);
                Ks[kdoff + j * 4 + 3][bcol] = to_tf32(f.w);
            }
        }
        // ---- stage V ----
        {
            int vtok = tid >> 2;
            int vdoff = (tid & 3) * 16;
            const float* vp = vbase + (size_t)(kc + vtok) * ND + vdoff;
#pragma unroll
            for (int j = 0; j < 4; j++) {
                float4 f = *(const float4*)(vp + j * 4);
                Vs[vtok][bc64p(vdoff + j * 4 + 0)] = to_tf32(f.x);
                Vs[vtok][bc64p(vdoff + j * 4 + 1)] = to_tf32(f.y);
                Vs[vtok][bc64p(vdoff + j * 4 + 2)] = to_tf32(f.z);
                Vs[vtok][bc64p(vdoff + j * 4 + 3)] = to_tf32(f.w);
            }
        }
        __syncthreads();

        // ---- S = Q K^T (16 rows x 32 cols per warp) ----
        float s[4][4];
#pragma unroll
        for (int nt = 0; nt < 4; nt++)
#pragma unroll
            for (int c = 0; c < 4; c++) s[nt][c] = 0.f;
#pragma unroll
        for (int ks = 0; ks < 8; ks++) {
            int kk = ks * 8;
            float4 b0 = *(const float4*)&Ks[kk + tg][g * 4];
            float4 b1 = *(const float4*)&Ks[kk + tg + 4][g * 4];
            float bf0[4] = {b0.x, b0.y, b0.z, b0.w};
            float bf1[4] = {b1.x, b1.y, b1.z, b1.w};
#pragma unroll
            for (int nt = 0; nt < 4; nt++) {
                asm volatile(
                    "mma.sync.aligned.m16n8k8.row.col.f32.tf32.tf32.f32 "
                    "{%0,%1,%2,%3}, {%4,%5,%6,%7}, {%8,%9}, {%0,%1,%2,%3};"
                    : "+f"(s[nt][0]), "+f"(s[nt][1]), "+f"(s[nt][2]), "+f"(s[nt][3])
                    : "r"(qfr[ks][0]), "r"(qfr[ks][1]), "r"(qfr[ks][2]), "r"(qfr[ks][3]),
                      "r"(__float_as_uint(bf0[nt])), "r"(__float_as_uint(bf1[nt])));
            }
        }
        // scale + causal mask (only diagonal-zone blocks need it)
#pragma unroll
        for (int nt = 0; nt < 4; nt++)
#pragma unroll
            for (int c = 0; c < 4; c++) s[nt][c] *= INV_SCALE;
        if (kc + 31 > q0) {
#pragma unroll
            for (int nt = 0; nt < 4; nt++) {
                int kbase2 = kc + nt * 8 + 2 * tg;
                if (kbase2 > qr0)     s[nt][0] = -INFINITY;
                if (kbase2 + 1 > qr0) s[nt][1] = -INFINITY;
                if (kbase2 > qr1)     s[nt][2] = -INFINITY;
                if (kbase2 + 1 > qr1) s[nt][3] = -INFINITY;
            }
        }
        // row max (reduce over nt, then over tg lanes)
        float mb0 = fmaxf(fmaxf(s[0][0], s[0][1]), fmaxf(s[1][0], s[1][1]));
        mb0 = fmaxf(mb0, fmaxf(fmaxf(s[2][0], s[2][1]), fmaxf(s[3][0], s[3][1])));
        float mb1 = fmaxf(fmaxf(s[0][2], s[0][3]), fmaxf(s[1][2], s[1][3]));
        mb1 = fmaxf(mb1, fmaxf(fmaxf(s[2][2], s[2][3]), fmaxf(s[3][2], s[3][3])));
        mb0 = fmaxf(mb0, __shfl_xor_sync(0xffffffffu, mb0, 1));
        mb0 = fmaxf(mb0, __shfl_xor_sync(0xffffffffu, mb0, 2));
        mb1 = fmaxf(mb1, __shfl_xor_sync(0xffffffffu, mb1, 1));
        mb1 = fmaxf(mb1, __shfl_xor_sync(0xffffffffu, mb1, 2));
        float mn0 = fmaxf(mo0, mb0), mn1 = fmaxf(mo1, mb1);
        float fc0 = __expf(mo0 - mn0), fc1 = __expf(mo1 - mn1);
        // exp + partial sums + store P
        float ps0 = 0.f, ps1 = 0.f;
#pragma unroll
        for (int nt = 0; nt < 4; nt++) {
            float e0 = __expf(s[nt][0] - mn0);
            float e1 = __expf(s[nt][1] - mn0);
            float e2 = __expf(s[nt][2] - mn1);
            float e3 = __expf(s[nt][3] - mn1);
            ps0 += e0 + e1; ps1 += e2 + e3;
            int kr = nt * 8 + 2 * tg;
            Ps[(kr)     * 72 + pc0] = to_tf32(e0);
            Ps[(kr + 1) * 72 + pc0] = to_tf32(e1);
            Ps[(kr)     * 72 + pc1] = to_tf32(e2);
            Ps[(kr + 1) * 72 + pc1] = to_tf32(e3);
        }
        ps0 += __shfl_xor_sync(0xffffffffu, ps0, 1);
        ps0 += __shfl_xor_sync(0xffffffffu, ps0, 2);
        ps1 += __shfl_xor_sync(0xffffffffu, ps1, 1);
        ps1 += __shfl_xor_sync(0xffffffffu, ps1, 2);
        l0 = l0 * fc0 + ps0; l1 = l1 * fc1 + ps1;
        mo0 = mn0; mo1 = mn1;
        // rescale O accumulators
#pragma unroll
        for (int nt = 0; nt < 8; nt++) {
            Oacc[nt][0] *= fc0; Oacc[nt][1] *= fc0;
            Oacc[nt][2] *= fc1; Oacc[nt][3] *= fc1;
        }
        __syncwarp();   // P is produced & consumed within the same warp

        // ---- O += P V (16 rows x 64 dims per warp) ----
#pragma unroll
        for (int ks = 0; ks < 4; ks++) {
            int kk = ks * 8;
            float2 x0 = *(const float2*)&Ps[(kk + tg) * 72 + pc0 /*m0+2g*/];
            float2 x1 = *(const float2*)&Ps[(kk + tg + 4) * 72 + pc0];
            uint32_t a0 = __float_as_uint(x0.x), a1 = __float_as_uint(x0.y);
            uint32_t a2 = __float_as_uint(x1.x), a3 = __float_as_uint(x1.y);
            float4 b0lo = *(const float4*)&Vs[kk + tg][g * 8];
            float4 b0hi = *(const float4*)&Vs[kk + tg][g * 8 + 4];
            float4 b1lo = *(const float4*)&Vs[kk + tg + 4][g * 8];
            float4 b1hi = *(const float4*)&Vs[kk + tg + 4][g * 8 + 4];
            float bf0[8] = {b0lo.x, b0lo.y, b0lo.z, b0lo.w, b0hi.x, b0hi.y, b0hi.z, b0hi.w};
            float bf1[8] = {b1lo.x, b1lo.y, b1lo.z, b1lo.w, b1hi.x, b1hi.y, b1hi.z, b1hi.w};
#pragma unroll
            for (int nt = 0; nt < 8; nt++) {
                asm volatile(
                    "mma.sync.aligned.m16n8k8.row.col.f32.tf32.tf32.f32 "
                    "{%0,%1,%2,%3}, {%4,%5,%6,%7}, {%8,%9}, {%0,%1,%2,%3};"
                    : "+f"(Oacc[nt][0]), "+f"(Oacc[nt][1]), "+f"(Oacc[nt][2]), "+f"(Oacc[nt][3])
                    : "r"(a0), "r"(a1), "r"(a2), "r"(a3),
                      "r"(__float_as_uint(bf0[nt])), "r"(__float_as_uint(bf1[nt])));
            }
        }
        __syncthreads();   // Ks/Vs reused next block
    }

    float i0 = 1.0f / l0, i1 = 1.0f / l1;
    float* ob = O + (size_t)b * NS * ND + h * NDH;
#pragma unroll
    for (int nt = 0; nt < 8; nt++) {
#pragma unroll
        for (int j = 0; j < 2; j++) {
            int d = nt * 8 + 2 * tg + j;
            ob[(size_t)qr0 * ND + d] = Oacc[nt][j] * i0;
            ob[(size_t)qr1 * ND + d] = Oacc[nt][2 + j] * i1;
        }
    }
}

// ---------------- loss: single-pass online logsumexp -------------------------
__global__ __launch_bounds__(512) void loss_row_k(const float* __restrict__ logits,
                                                  const int* __restrict__ idx,
                                                  const int* __restrict__ mask,
                                                  float* __restrict__ nll) {
    int row = blockIdx.x;
    int b = row / NS, s = row % NS;
    const float* lr = logits + (size_t)row * NV;
    int tid = threadIdx.x;
    __shared__ float redm[512];
    __shared__ float reds[512];
    float m = -INFINITY, sum = 0.f;
    for (int i = tid; i < NV; i += 512) {
        float x = lr[i];
        if (x > m) { sum = sum * __expf(m - x) + 1.f; m = x; }
        else       { sum += __expf(x - m); }
    }
    redm[tid] = m; reds[tid] = sum;
    __syncthreads();
    for (int o = 256; o > 0; o >>= 1) {
        if (tid < o) {
            float m2 = redm[tid + o], s2 = reds[tid + o];
            float m1 = redm[tid],     s1 = reds[tid];
            float M = fmaxf(m1, m2);
            redm[tid] = M;
            reds[tid] = s1 * __expf(m1 - M) + s2 * __expf(m2 - M);
        }
        __syncthreads();
    }
    if (tid == 0) {
        int tgt = idx[b * (NS + 1) + s + 1];
        float lse = redm[0] + logf(reds[0]);
        nll[row] = (lse - lr[tgt]) * (float)mask[row];
    }
}

__global__ __launch_bounds__(1024) void loss_final_k(const float* __restrict__ nll,
                                                     float* __restrict__ out) {
    __shared__ float red[1024];
    int tid = threadIdx.x;
    red[tid] = nll[tid] + nll[tid + 1024];
    __syncthreads();
    for (int o = 512; o > 0; o >>= 1) { if (tid < o) red[tid] += red[tid + o]; __syncthreads(); }
    if (tid == 0) out[0] = red[0] * (1.0f / (float)NBS);
}

// ---------------- host orchestration -----------------------------------------
extern "C" void kernel_launch(void* const* d_in, const int* in_sizes, int n_in,
                              void* d_out, int out_size) {
    const int*   idx  = (const int*)d_in[0];
    const int*   mask = (const int*)d_in[1];
    const float* tok  = (const float*)d_in[2];
    const float* pos  = (const float*)d_in[3];
    const float* Wq   = (const float*)d_in[4];
    const float* bq   = (const float*)d_in[5];
    const float* Wk   = (const float*)d_in[6];
    const float* bk   = (const float*)d_in[7];
    const float* Wv   = (const float*)d_in[8];
    const float* bv   = (const float*)d_in[9];
    const float* Wo   = (const float*)d_in[10];
    const float* bo   = (const float*)d_in[11];
    const float* ln1g = (const float*)d_in[12];
    const float* ln1b = (const float*)d_in[13];
    const float* W1   = (const float*)d_in[14];
    const float* b1   = (const float*)d_in[15];
    const float* W2   = (const float*)d_in[16];
    const float* b2   = (const float*)d_in[17];
    const float* ln2g = (const float*)d_in[18];
    const float* ln2b = (const float*)d_in[19];
    const float* lnfg = (const float*)d_in[20];
    const float* lnfb = (const float*)d_in[21];
    const float* headw= (const float*)d_in[22];
    float* out = (float*)d_out;

    float *x, *h, *q, *k, *v, *o, *ff, *nll;
    cudaGetSymbolAddress((void**)&x,   g_x);
    cudaGetSymbolAddress((void**)&h,   g_h);
    cudaGetSymbolAddress((void**)&q,   g_q);
    cudaGetSymbolAddress((void**)&k,   g_k);
    cudaGetSymbolAddress((void**)&v,   g_v);
    cudaGetSymbolAddress((void**)&o,   g_o);
    cudaGetSymbolAddress((void**)&ff,  g_ff);
    cudaGetSymbolAddress((void**)&nll, g_nll);

    embed_k<<<NBS, 256>>>(idx, mask, tok, pos, x);

    dim3 gQKV(ND / 64, NBS / 128, 3);   // 384 CTAs
    dim3 gDD(ND / 64, NBS / 128);       // 128 CTAs
    dim3 gDF(NFF / 128, NBS / 128);     // 256 CTAs
    dim3 gFA(NS / 64, NB * NH);         // 256 CTAs

    for (int l = 0; l < NL; l++) {
        const float* wq = Wq + (size_t)l * ND * ND;
        const float* wk = Wk + (size_t)l * ND * ND;
        const float* wv = Wv + (size_t)l * ND * ND;
        const float* wo = Wo + (size_t)l * ND * ND;
        const float* w1 = W1 + (size_t)l * ND * NFF;
        const float* w2 = W2 + (size_t)l * NFF * ND;

        ln_k<<<NBS, 256>>>(x, ln1g + l * ND, ln1b + l * ND, h);
        TriPtrs t;
        t.w[0] = wq; t.w[1] = wk; t.w[2] = wv;
        t.b[0] = bq + l * ND; t.b[1] = bk + l * ND; t.b[2] = bv + l * ND;
        t.c[0] = q; t.c[1] = k; t.c[2] = v;
        gemm_qkv<<<gQKV, 256>>>(h, t, NBS, ND, ND);
        attn_flash<<<gFA, 128>>>(q, k, v, o);
        gemm_tc<0, true, true, 64, true, false><<<gDD, 256>>>(o, wo, bo + l * ND, x, x, NBS, ND, ND);
        ln_k<<<NBS, 256>>>(x, ln2g + l * ND, ln2b + l * ND, h);
        gemm_tc<1, true, false, 128, true, false><<<gDF, 256>>>(h, w1, b1 + l * NFF, nullptr, ff, NBS, NFF, ND);
        gemm_tc<0, true, true, 64, true, false><<<gDD, 256>>>(ff, w2, b2 + l * ND, x, x, NBS, ND, NFF);
    }

    ln_k<<<NBS, 256>>>(x, lnfg, lnfb, h);
    dim3 gHead(NBS / 128, (NV + 127) / 128);   // M-tiles fastest -> B reused in L2
    gemm_tc<0, false, false, 128, false, true><<<gHead, 256>>>(h, headw, nullptr, nullptr, out, NBS, NV, ND);

    loss_row_k<<<NBS, 512>>>(out, idx, mask, nll);
    loss_final_k<<<1, 1024>>>(nll, out + (size_t)NBS * NV);
}

// round 13
// speedup vs baseline: 2.0848x; 1.0173x over previous
#include <cuda_runtime.h>
#include <cuda_bf16.h>
#include <math.h>
#include <stdint.h>

// Problem dims
constexpr int NB  = 2;
constexpr int NS  = 1024;
constexpr int ND  = 512;
constexpr int NH  = 8;
constexpr int NDH = 64;
constexpr int NL  = 6;
constexpr int NV  = 50257;
constexpr int NBS = NB * NS;      // 2048
constexpr int NFF = 4 * ND;       // 2048
constexpr float INV_SCALE = 0.04419417382415922f; // 1/sqrt(512)

// ---------------- scratch (static device globals; no allocation) -------------
__device__ float g_x[NBS * ND];
__device__ float g_h[NBS * ND];
__device__ float g_q[NBS * ND];
__device__ float g_k[NBS * ND];
__device__ float g_v[NBS * ND];
__device__ float g_o[NBS * ND];
__device__ float g_ff[NBS * NFF];
__device__ float g_nll[NBS];

__device__ __forceinline__ float to_tf32(float x) {
    uint32_t u;
    asm("cvt.rna.tf32.f32 %0, %1;" : "=r"(u) : "f"(x));
    return __uint_as_float(u);
}

// Fragment-friendly column permutations.
__device__ __forceinline__ int ac16(int m) {
    return (m & ~15) | ((m & 7) << 1) | ((m >> 3) & 1);
}
__device__ __forceinline__ int bc32(int n) {
    return (n & ~31) | ((n & 7) << 2) | ((n >> 3) & 3);
}
__device__ __forceinline__ int bc64p(int n) {
    return ((n & 7) << 3) | ((n >> 3) & 7);
}

// ---------------- embedding --------------------------------------------------
__global__ void embed_k(const int* __restrict__ idx, const int* __restrict__ mask,
                        const float* __restrict__ tok, const float* __restrict__ pos,
                        float* __restrict__ x) {
    int row = blockIdx.x;
    int b = row / NS, s = row % NS;
    int t = idx[b * (NS + 1) + s];
    float m = (float)mask[row];
    const float* tr = tok + (size_t)t * ND;
    const float* pr = pos + (size_t)s * ND;
    float* xr = x + (size_t)row * ND;
    for (int d = threadIdx.x; d < ND; d += blockDim.x)
        xr[d] = (tr[d] + pr[d]) * m;
}

// ---------------- layernorm --------------------------------------------------
__global__ __launch_bounds__(256) void ln_k(const float* __restrict__ x,
                                            const float* __restrict__ g,
                                            const float* __restrict__ be,
                                            float* __restrict__ out) {
    int row = blockIdx.x;
    int tid = threadIdx.x;
    const float* xr = x + (size_t)row * ND;
    float v0 = xr[tid], v1 = xr[tid + 256];
    __shared__ float red[256];
    red[tid] = v0 + v1;
    __syncthreads();
    for (int o = 128; o > 0; o >>= 1) { if (tid < o) red[tid] += red[tid + o]; __syncthreads(); }
    float mean = red[0] * (1.0f / ND);
    __syncthreads();
    float d0 = v0 - mean, d1 = v1 - mean;
    red[tid] = d0 * d0 + d1 * d1;
    __syncthreads();
    for (int o = 128; o > 0; o >>= 1) { if (tid < o) red[tid] += red[tid + o]; __syncthreads(); }
    float inv = rsqrtf(red[0] * (1.0f / ND) + 1e-5f);
    float* orow = out + (size_t)row * ND;
    orow[tid]       = d0 * inv * g[tid]       + be[tid];
    orow[tid + 256] = d1 * inv * g[tid + 256] + be[tid + 256];
}

// ---------------- TF32 tensor-core GEMM, double-buffered, vectorized frags ---
template <int ACT, bool HAS_BIAS, bool HAS_RES, int BN, bool BALIGN>
__device__ __forceinline__ void gemm_body(const float* __restrict__ A,
                                          const float* __restrict__ Bm,
                                          const float* __restrict__ bias,
                                          const float* __restrict__ Res,
                                          float* __restrict__ C,
                                          int M, int N, int K,
                                          int m0, int n0) {
    constexpr int BM = 128, BK = 16;
    constexpr int WARPS_N = (BN == 128) ? 4 : 2;
    constexpr int WARPS_M = 8 / WARPS_N;
    constexpr int WM = BM / WARPS_M;
    constexpr int WN = BN / WARPS_N;
    constexpr int MT = WM / 16;
    constexpr int NT = WN / 8;
    constexpr int AP = BM + 8;
    constexpr int BP = BN + 8;

    __shared__ float As[2][BK][AP];
    __shared__ float Bs[2][BK][BP];

    int tid = threadIdx.x;
    int warp = tid >> 5;
    int lane = tid & 31;
    int g  = lane >> 2;
    int tg = lane & 3;
    int warpM = warp % WARPS_M;
    int warpN = warp / WARPS_M;

    float acc[MT][NT][4];
#pragma unroll
    for (int i = 0; i < MT; i++)
#pragma unroll
        for (int j = 0; j < NT; j++)
#pragma unroll
            for (int c = 0; c < 4; c++) acc[i][j][c] = 0.f;

    int arow = tid >> 1, ak = (tid & 1) * 8;
    int acol = ac16(arow);
    int br128 = tid >> 5, bc128 = (tid & 31) * 4;
    int br64  = tid >> 4, bc64  = (tid & 15) * 4;

    float4 ra0, ra1, rb0, rb1;

    auto loadA = [&](int k0) {
        const float* ap = A + (size_t)(m0 + arow) * K + k0 + ak;
        ra0 = *(const float4*)ap;
        ra1 = *(const float4*)(ap + 4);
    };
    auto loadB = [&](int k0) {
        if (BN == 128) {
            if (BALIGN) {
                rb0 = *(const float4*)(Bm + (size_t)(k0 + br128) * N + n0 + bc128);
                rb1 = *(const float4*)(Bm + (size_t)(k0 + br128 + 8) * N + n0 + bc128);
            } else {
                const float* bp0 = Bm + (size_t)(k0 + br128) * N;
                const float* bp1 = Bm + (size_t)(k0 + br128 + 8) * N;
                int c0 = n0 + bc128;
                rb0.x = (c0 + 0 < N) ? bp0[c0 + 0] : 0.f;
                rb0.y = (c0 + 1 < N) ? bp0[c0 + 1] : 0.f;
                rb0.z = (c0 + 2 < N) ? bp0[c0 + 2] : 0.f;
                rb0.w = (c0 + 3 < N) ? bp0[c0 + 3] : 0.f;
                rb1.x = (c0 + 0 < N) ? bp1[c0 + 0] : 0.f;
                rb1.y = (c0 + 1 < N) ? bp1[c0 + 1] : 0.f;
                rb1.z = (c0 + 2 < N) ? bp1[c0 + 2] : 0.f;
                rb1.w = (c0 + 3 < N) ? bp1[c0 + 3] : 0.f;
            }
        } else {
            rb0 = *(const float4*)(Bm + (size_t)(k0 + br64) * N + n0 + bc64);
        }
    };
    auto storeA = [&](int s) {
        As[s][ak + 0][acol] = to_tf32(ra0.x); As[s][ak + 1][acol] = to_tf32(ra0.y);
        As[s][ak + 2][acol] = to_tf32(ra0.z); As[s][ak + 3][acol] = to_tf32(ra0.w);
        As[s][ak + 4][acol] = to_tf32(ra1.x); As[s][ak + 5][acol] = to_tf32(ra1.y);
        As[s][ak + 6][acol] = to_tf32(ra1.z); As[s][ak + 7][acol] = to_tf32(ra1.w);
    };
    auto storeB = [&](int s) {
        if (BN == 128) {
            Bs[s][br128][bc32(bc128 + 0)] = to_tf32(rb0.x);
            Bs[s][br128][bc32(bc128 + 1)] = to_tf32(rb0.y);
            Bs[s][br128][bc32(bc128 + 2)] = to_tf32(rb0.z);
            Bs[s][br128][bc32(bc128 + 3)] = to_tf32(rb0.w);
            Bs[s][br128 + 8][bc32(bc128 + 0)] = to_tf32(rb1.x);
            Bs[s][br128 + 8][bc32(bc128 + 1)] = to_tf32(rb1.y);
            Bs[s][br128 + 8][bc32(bc128 + 2)] = to_tf32(rb1.z);
            Bs[s][br128 + 8][bc32(bc128 + 3)] = to_tf32(rb1.w);
        } else {
            Bs[s][br64][bc32(bc64 + 0)] = to_tf32(rb0.x);
            Bs[s][br64][bc32(bc64 + 1)] = to_tf32(rb0.y);
            Bs[s][br64][bc32(bc64 + 2)] = to_tf32(rb0.z);
            Bs[s][br64][bc32(bc64 + 3)] = to_tf32(rb0.w);
        }
    };

    int nTiles = K / BK;
    loadA(0); loadB(0);
    storeA(0); storeB(0);
    __syncthreads();

    for (int t = 0; t < nTiles; t++) {
        int cur = t & 1, nxt = cur ^ 1;
        bool more = (t + 1 < nTiles);
        if (more) { loadA((t + 1) * BK); loadB((t + 1) * BK); }

#pragma unroll
        for (int kk = 0; kk < BK; kk += 8) {
            uint32_t afr[MT][4];
            float bfr0[NT], bfr1[NT];
#pragma unroll
            for (int mt = 0; mt < MT; mt++) {
                int mc = warpM * WM + mt * 16 + g * 2;
                float2 x0 = *(const float2*)&As[cur][kk + tg][mc];
                float2 x1 = *(const float2*)&As[cur][kk + tg + 4][mc];
                afr[mt][0] = __float_as_uint(x0.x);
                afr[mt][1] = __float_as_uint(x0.y);
                afr[mt][2] = __float_as_uint(x1.x);
                afr[mt][3] = __float_as_uint(x1.y);
            }
            {
                int nc = warpN * WN + g * 4;
                float4 b0 = *(const float4*)&Bs[cur][kk + tg][nc];
                float4 b1 = *(const float4*)&Bs[cur][kk + tg + 4][nc];
                bfr0[0] = b0.x; bfr0[1] = b0.y; bfr0[2] = b0.z; bfr0[3] = b0.w;
                bfr1[0] = b1.x; bfr1[1] = b1.y; bfr1[2] = b1.z; bfr1[3] = b1.w;
            }
#pragma unroll
            for (int mt = 0; mt < MT; mt++)
#pragma unroll
                for (int nt = 0; nt < NT; nt++) {
                    asm volatile(
                        "mma.sync.aligned.m16n8k8.row.col.f32.tf32.tf32.f32 "
                        "{%0,%1,%2,%3}, {%4,%5,%6,%7}, {%8,%9}, {%0,%1,%2,%3};"
                        : "+f"(acc[mt][nt][0]), "+f"(acc[mt][nt][1]),
                          "+f"(acc[mt][nt][2]), "+f"(acc[mt][nt][3])
                        : "r"(afr[mt][0]), "r"(afr[mt][1]),
                          "r"(afr[mt][2]), "r"(afr[mt][3]),
                          "r"(__float_as_uint(bfr0[nt])), "r"(__float_as_uint(bfr1[nt])));
                }
        }
        if (more) { storeA(nxt); storeB(nxt); }
        __syncthreads();
    }

#pragma unroll
    for (int mt = 0; mt < MT; mt++) {
#pragma unroll
        for (int nt = 0; nt < NT; nt++) {
            int row0 = m0 + warpM * WM + mt * 16 + g;
            int col0 = n0 + warpN * WN + nt * 8 + 2 * tg;
#pragma unroll
            for (int hh = 0; hh < 2; hh++) {
                int row = row0 + hh * 8;
#pragma unroll
                for (int j = 0; j < 2; j++) {
                    int col = col0 + j;
                    if (col < N) {
                        float v = acc[mt][nt][hh * 2 + j];
                        if (HAS_BIAS) v += bias[col];
                        if (ACT == 1) v = 0.5f * v * (1.0f + erff(v * 0.70710678118654752f));
                        if (HAS_RES) v += Res[(size_t)row * N + col];
                        C[(size_t)row * N + col] = v;
                    }
                }
            }
        }
    }
}

template <int ACT, bool HAS_BIAS, bool HAS_RES, int BN, bool BALIGN, bool SWAP>
__global__ __launch_bounds__(256) void gemm_tc(const float* __restrict__ A,
                                               const float* __restrict__ Bm,
                                               const float* __restrict__ bias,
                                               const float* __restrict__ Res,
                                               float* __restrict__ C,
                                               int M, int N, int K) {
    int m0 = (SWAP ? blockIdx.x : blockIdx.y) * 128;
    int n0 = (SWAP ? blockIdx.y : blockIdx.x) * BN;
    gemm_body<ACT, HAS_BIAS, HAS_RES, BN, BALIGN>(A, Bm, bias, Res, C, M, N, K, m0, n0);
}

struct TriPtrs {
    const float* w[3];
    const float* b[3];
    float*       c[3];
};
__global__ __launch_bounds__(256) void gemm_qkv(const float* __restrict__ A,
                                                TriPtrs t, int M, int N, int K) {
    int z = blockIdx.z;
    gemm_body<0, true, false, 64, true>(
        A, t.w[z], t.b[z], nullptr, t.c[z], M, N, K, blockIdx.y * 128, blockIdx.x * 64);
}

// ---------------- fully fused flash attention, 2 warp-groups (split-K) -------
// grid (NS/64, NB*NH), 256 threads (8 warps = 2 groups of 4).
// Group g processes k-blocks g, g+2, ... (nblk always even -> balanced).
// Flat smem carving (floats), ALL row pitches 16B-multiples for float4:
//   K pitch 36 (144 B), V pitch 72 (288 B), P pitch 72 (aliases K region).
//   K0 [0, 2304)   K1 [2304, 4608)     (also P0/P1; also merge OBuf rows)
//   V0 [4608, 6912) V1 [6912, 9216)
//   m1 [9216, 9280) l1 [9280, 9344)
// Q staged transiently at offset 0 (pitch 72, 4608 floats) before the loop.
__global__ __launch_bounds__(256) void attn_flash(const float* __restrict__ Q,
                                                  const float* __restrict__ Kg,
                                                  const float* __restrict__ Vg,
                                                  float* __restrict__ O) {
    __shared__ __align__(16) float sm[9344];

    int q0 = (gridDim.x - 1 - blockIdx.x) * 64;   // longest first
    int bh = blockIdx.y;
    int b = bh >> 3, h = bh & 7;
    int tid = threadIdx.x;
    int warp = tid >> 5;
    int grp = warp >> 2;          // 0 or 1
    int wl = warp & 3;            // warp in group
    int lane = tid & 31;
    int gl = lane >> 2, tg = lane & 3;
    int m0 = wl * 16;
    int lt = tid & 127;           // thread id within group

    const float* qbase = Q + (size_t)b * NS * ND + h * NDH;
    const float* kbase = Kg + (size_t)b * NS * ND + h * NDH;
    const float* vbase = Vg + (size_t)b * NS * ND + h * NDH;

    // ---- stage Q tile (64 rows x 64 dims), layout [d][ac16(qrow)], pitch 72 --
    {
        int row = tid >> 2;
        int doff = (tid & 3) * 16;
        int acol = ac16(row);
        const float* qp = qbase + (size_t)(q0 + row) * ND + doff;
#pragma unroll
        for (int j = 0; j < 4; j++) {
            float4 f = *(const float4*)(qp + j * 4);
            sm[(doff + j * 4 + 0) * 72 + acol] = to_tf32(f.x);
            sm[(doff + j * 4 + 1) * 72 + acol] = to_tf32(f.y);
            sm[(doff + j * 4 + 2) * 72 + acol] = to_tf32(f.z);
            sm[(doff + j * 4 + 3) * 72 + acol] = to_tf32(f.w);
        }
    }
    __syncthreads();

    // ---- preload Q fragments ----
    uint32_t qfr[8][4];
#pragma unroll
    for (int ks = 0; ks < 8; ks++) {
        int kk = ks * 8;
        float2 x0 = *(const float2*)&sm[(kk + tg) * 72 + m0 + 2 * gl];
        float2 x1 = *(const float2*)&sm[(kk + tg + 4) * 72 + m0 + 2 * gl];
        qfr[ks][0] = __float_as_uint(x0.x);
        qfr[ks][1] = __float_as_uint(x0.y);
        qfr[ks][2] = __float_as_uint(x1.x);
        qfr[ks][3] = __float_as_uint(x1.y);
    }
    __syncthreads();   // Q smem now free for K/P reuse

    float* Ksm = sm + grp * 2304;          // [d][bc32(tok)] pitch 36
    float* Psm = Ksm;                      // [k][ac16(qrow)] pitch 72 (aliased)
    float* Vsm = sm + 4608 + grp * 2304;   // [tok][bc64p(d)] pitch 72
    float* m1_s = sm + 9216;
    float* l1_s = sm + 9280;

    float Oacc[8][4];
#pragma unroll
    for (int nt = 0; nt < 8; nt++)
#pragma unroll
        for (int c = 0; c < 4; c++) Oacc[nt][c] = 0.f;

    float mo0 = -1e30f, mo1 = -1e30f, l0 = 0.f, l1 = 0.f;
    int qr0 = q0 + m0 + gl, qr1 = qr0 + 8;
    int pc0 = m0 + 2 * gl, pc1 = pc0 + 1;

    int nblk = (q0 + 64) >> 5;   // always even
    int barid = 1 + grp;

    for (int blk = grp; blk < nblk; blk += 2) {
        int kc = blk << 5;
        // ---- stage K ----
        {
            int ktok = lt & 31;
            int kdoff = (lt >> 5) * 16;
            int bcol = bc32(ktok);
            const float* kp = kbase + (size_t)(kc + ktok) * ND + kdoff;
#pragma unroll
            for (int j = 0; j < 4; j++) {
                float4 f = *(const float4*)(kp + j * 4);
                Ksm[(kdoff + j * 4 + 0) * 36 + bcol] = to_tf32(f.x);
                Ksm[(kdoff + j * 4 + 1) * 36 + bcol] = to_tf32(f.y);
                Ksm[(kdoff + j * 4 + 2) * 36 + bcol] = to_tf32(f.z);
                Ksm[(kdoff + j * 4 + 3) * 36 + bcol] = to_tf32(f.w);
            }
        }
        // ---- stage V ----
        {
            int vtok = lt >> 2;
            int vdoff = (lt & 3) * 16;
            const float* vp = vbase + (size_t)(kc + vtok) * ND + vdoff;
#pragma unroll
            for (int j = 0; j < 4; j++) {
                float4 f = *(const float4*)(vp + j * 4);
                Vsm[vtok * 72 + bc64p(vdoff + j * 4 + 0)] = to_tf32(f.x);
                Vsm[vtok * 72 + bc64p(vdoff + j * 4 + 1)] = to_tf32(f.y);
                Vsm[vtok * 72 + bc64p(vdoff + j * 4 + 2)] = to_tf32(f.z);
                Vsm[vtok * 72 + bc64p(vdoff + j * 4 + 3)] = to_tf32(f.w);
            }
        }
        asm volatile("bar.sync %0, 128;" :: "r"(barid) : "memory");

        // ---- S = Q K^T (16 rows x 32 cols per warp) ----
        float s[4][4];
#pragma unroll
        for (int nt = 0; nt < 4; nt++)
#pragma unroll
            for (int c = 0; c < 4; c++) s[nt][c] = 0.f;
#pragma unroll
        for (int ks = 0; ks < 8; ks++) {
            int kk = ks * 8;
            float4 b0 = *(const float4*)&Ksm[(kk + tg) * 36 + gl * 4];
            float4 b1 = *(const float4*)&Ksm[(kk + tg + 4) * 36 + gl * 4];
            float bf0[4] = {b0.x, b0.y, b0.z, b0.w};
            float bf1[4] = {b1.x, b1.y, b1.z, b1.w};
#pragma unroll
            for (int nt = 0; nt < 4; nt++) {
                asm volatile(
                    "mma.sync.aligned.m16n8k8.row.col.f32.tf32.tf32.f32 "
                    "{%0,%1,%2,%3}, {%4,%5,%6,%7}, {%8,%9}, {%0,%1,%2,%3};"
                    : "+f"(s[nt][0]), "+f"(s[nt][1]), "+f"(s[nt][2]), "+f"(s[nt][3])
                    : "r"(qfr[ks][0]), "r"(qfr[ks][1]), "r"(qfr[ks][2]), "r"(qfr[ks][3]),
                      "r"(__float_as_uint(bf0[nt])), "r"(__float_as_uint(bf1[nt])));
            }
        }
#pragma unroll
        for (int nt = 0; nt < 4; nt++)
#pragma unroll
            for (int c = 0; c < 4; c++) s[nt][c] *= INV_SCALE;
        if (kc + 31 > q0) {
#pragma unroll
            for (int nt = 0; nt < 4; nt++) {
                int kb = kc + nt * 8 + 2 * tg;
                if (kb > qr0)     s[nt][0] = -INFINITY;
                if (kb + 1 > qr0) s[nt][1] = -INFINITY;
                if (kb > qr1)     s[nt][2] = -INFINITY;
                if (kb + 1 > qr1) s[nt][3] = -INFINITY;
            }
        }
        // row max + online stats (mo >= -1e30 keeps exp args finite)
        float mb0 = fmaxf(fmaxf(s[0][0], s[0][1]), fmaxf(s[1][0], s[1][1]));
        mb0 = fmaxf(mb0, fmaxf(fmaxf(s[2][0], s[2][1]), fmaxf(s[3][0], s[3][1])));
        float mb1 = fmaxf(fmaxf(s[0][2], s[0][3]), fmaxf(s[1][2], s[1][3]));
        mb1 = fmaxf(mb1, fmaxf(fmaxf(s[2][2], s[2][3]), fmaxf(s[3][2], s[3][3])));
        mb0 = fmaxf(mb0, __shfl_xor_sync(0xffffffffu, mb0, 1));
        mb0 = fmaxf(mb0, __shfl_xor_sync(0xffffffffu, mb0, 2));
        mb1 = fmaxf(mb1, __shfl_xor_sync(0xffffffffu, mb1, 1));
        mb1 = fmaxf(mb1, __shfl_xor_sync(0xffffffffu, mb1, 2));
        float mn0 = fmaxf(mo0, mb0), mn1 = fmaxf(mo1, mb1);
        float fc0 = __expf(mo0 - mn0), fc1 = __expf(mo1 - mn1);
        float e[4][4];
        float ps0 = 0.f, ps1 = 0.f;
#pragma unroll
        for (int nt = 0; nt < 4; nt++) {
            e[nt][0] = __expf(s[nt][0] - mn0);
            e[nt][1] = __expf(s[nt][1] - mn0);
            e[nt][2] = __expf(s[nt][2] - mn1);
            e[nt][3] = __expf(s[nt][3] - mn1);
            ps0 += e[nt][0] + e[nt][1];
            ps1 += e[nt][2] + e[nt][3];
        }
        ps0 += __shfl_xor_sync(0xffffffffu, ps0, 1);
        ps0 += __shfl_xor_sync(0xffffffffu, ps0, 2);
        ps1 += __shfl_xor_sync(0xffffffffu, ps1, 1);
        ps1 += __shfl_xor_sync(0xffffffffu, ps1, 2);
        l0 = l0 * fc0 + ps0; l1 = l1 * fc1 + ps1;
        mo0 = mn0; mo1 = mn1;
#pragma unroll
        for (int nt = 0; nt < 8; nt++) {
            Oacc[nt][0] *= fc0; Oacc[nt][1] *= fc0;
            Oacc[nt][2] *= fc1; Oacc[nt][3] *= fc1;
        }

        // all group warps must finish READING Ksm before P overwrites it
        asm volatile("bar.sync %0, 128;" :: "r"(barid) : "memory");
#pragma unroll
        for (int nt = 0; nt < 4; nt++) {
            int kr = nt * 8 + 2 * tg;
            Psm[(kr)     * 72 + pc0] = to_tf32(e[nt][0]);
            Psm[(kr + 1) * 72 + pc0] = to_tf32(e[nt][1]);
            Psm[(kr)     * 72 + pc1] = to_tf32(e[nt][2]);
            Psm[(kr + 1) * 72 + pc1] = to_tf32(e[nt][3]);
        }
        __syncwarp();   // P produced & consumed within the same warp columns

        // ---- O += P V ----
#pragma unroll
        for (int ks = 0; ks < 4; ks++) {
            int kk = ks * 8;
            float2 x0 = *(const float2*)&Psm[(kk + tg) * 72 + pc0];
            float2 x1 = *(const float2*)&Psm[(kk + tg + 4) * 72 + pc0];
            uint32_t a0 = __float_as_uint(x0.x), a1 = __float_as_uint(x0.y);
            uint32_t a2 = __float_as_uint(x1.x), a3 = __float_as_uint(x1.y);
            float4 b0lo = *(const float4*)&Vsm[(kk + tg) * 72 + gl * 8];
            float4 b0hi = *(const float4*)&Vsm[(kk + tg) * 72 + gl * 8 + 4];
            float4 b1lo = *(const float4*)&Vsm[(kk + tg + 4) * 72 + gl * 8];
            float4 b1hi = *(const float4*)&Vsm[(kk + tg + 4) * 72 + gl * 8 + 4];
            float bf0[8] = {b0lo.x, b0lo.y, b0lo.z, b0lo.w, b0hi.x, b0hi.y, b0hi.z, b0hi.w};
            float bf1[8] = {b1lo.x, b1lo.y, b1lo.z, b1lo.w, b1hi.x, b1hi.y, b1hi.z, b1hi.w};
#pragma unroll
            for (int nt = 0; nt < 8; nt++) {
                asm volatile(
                    "mma.sync.aligned.m16n8k8.row.col.f32.tf32.tf32.f32 "
                    "{%0,%1,%2,%3}, {%4,%5,%6,%7}, {%8,%9}, {%0,%1,%2,%3};"
                    : "+f"(Oacc[nt][0]), "+f"(Oacc[nt][1]), "+f"(Oacc[nt][2]), "+f"(Oacc[nt][3])
                    : "r"(a0), "r"(a1), "r"(a2), "r"(a3),
                      "r"(__float_as_uint(bf0[nt])), "r"(__float_as_uint(bf1[nt])));
            }
        }
        asm volatile("bar.sync %0, 128;" :: "r"(barid) : "memory");  // buffers reused
    }

    // ---- merge group 1 into group 0 (OBuf pitch 72 over K0+K1 region) ----
    __syncthreads();
    int r0 = m0 + gl, r1 = r0 + 8;
    if (grp == 1) {
        if (tg == 0) {
            m1_s[r0] = mo0; m1_s[r1] = mo1;
            l1_s[r0] = l0;  l1_s[r1] = l1;
        }
#pragma unroll
        for (int nt = 0; nt < 8; nt++) {
            int d = nt * 8 + 2 * tg;
            *(float2*)&sm[r0 * 72 + d] = make_float2(Oacc[nt][0], Oacc[nt][1]);
            *(float2*)&sm[r1 * 72 + d] = make_float2(Oacc[nt][2], Oacc[nt][3]);
        }
    }
    __syncthreads();
    if (grp == 0) {
        float m1v0 = m1_s[r0], m1v1 = m1_s[r1];
        float l1v0 = l1_s[r0], l1v1 = l1_s[r1];
        float mf0 = fmaxf(mo0, m1v0), mf1 = fmaxf(mo1, m1v1);
        float a0c = __expf(mo0 - mf0), b0c = __expf(m1v0 - mf0);
        float a1c = __expf(mo1 - mf1), b1c = __expf(m1v1 - mf1);
        float inv0 = 1.0f / (l0 * a0c + l1v0 * b0c);
        float inv1 = 1.0f / (l1 * a1c + l1v1 * b1c);
        float* ob = O + (size_t)b * NS * ND + h * NDH;
#pragma unroll
        for (int nt = 0; nt < 8; nt++) {
            int d = nt * 8 + 2 * tg;
            float2 o10 = *(const float2*)&sm[r0 * 72 + d];
            float2 o11 = *(const float2*)&sm[r1 * 72 + d];
            float2 w0 = make_float2((Oacc[nt][0] * a0c + o10.x * b0c) * inv0,
                                    (Oacc[nt][1] * a0c + o10.y * b0c) * inv0);
            float2 w1 = make_float2((Oacc[nt][2] * a1c + o11.x * b1c) * inv1,
                                    (Oacc[nt][3] * a1c + o11.y * b1c) * inv1);
            *(float2*)&ob[(size_t)qr0 * ND + d] = w0;
            *(float2*)&ob[(size_t)qr1 * ND + d] = w1;
        }
    }
}

// ---------------- loss: single-pass online logsumexp -------------------------
__global__ __launch_bounds__(512) void loss_row_k(const float* __restrict__ logits,
                                                  const int* __restrict__ idx,
                                                  const int* __restrict__ mask,
                                                  float* __restrict__ nll) {
    int row = blockIdx.x;
    int b = row / NS, s = row % NS;
    const float* lr = logits + (size_t)row * NV;
    int tid = threadIdx.x;
    __shared__ float redm[512];
    __shared__ float reds[512];
    float m = -INFINITY, sum = 0.f;
    for (int i = tid; i < NV; i += 512) {
        float x = lr[i];
        if (x > m) { sum = sum * __expf(m - x) + 1.f; m = x; }
        else       { sum += __expf(x - m); }
    }
    redm[tid] = m; reds[tid] = sum;
    __syncthreads();
    for (int o = 256; o > 0; o >>= 1) {
        if (tid < o) {
            float m2 = redm[tid + o], s2 = reds[tid + o];
            float m1 = redm[tid],     s1 = reds[tid];
            float M = fmaxf(m1, m2);
            redm[tid] = M;
            reds[tid] = s1 * __expf(m1 - M) + s2 * __expf(m2 - M);
        }
        __syncthreads();
    }
    if (tid == 0) {
        int tgt = idx[b * (NS + 1) + s + 1];
        float lse = redm[0] + logf(reds[0]);
        nll[row] = (lse - lr[tgt]) * (float)mask[row];
    }
}

__global__ __launch_bounds__(1024) void loss_final_k(const float* __restrict__ nll,
                                                     float* __restrict__ out) {
    __shared__ float red[1024];
    int tid = threadIdx.x;
    red[tid] = nll[tid] + nll[tid + 1024];
    __syncthreads();
    for (int o = 512; o > 0; o >>= 1) { if (tid < o) red[tid] += red[tid + o]; __syncthreads(); }
    if (tid == 0) out[0] = red[0] * (1.0f / (float)NBS);
}

// ---------------- host orchestration -----------------------------------------
extern "C" void kernel_launch(void* const* d_in, const int* in_sizes, int n_in,
                              void* d_out, int out_size) {
    const int*   idx  = (const int*)d_in[0];
    const int*   mask = (const int*)d_in[1];
    const float* tok  = (const float*)d_in[2];
    const float* pos  = (const float*)d_in[3];
    const float* Wq   = (const float*)d_in[4];
    const float* bq   = (const float*)d_in[5];
    const float* Wk   = (const float*)d_in[6];
    const float* bk   = (const float*)d_in[7];
    const float* Wv   = (const float*)d_in[8];
    const float* bv   = (const float*)d_in[9];
    const float* Wo   = (const float*)d_in[10];
    const float* bo   = (const float*)d_in[11];
    const float* ln1g = (const float*)d_in[12];
    const float* ln1b = (const float*)d_in[13];
    const float* W1   = (const float*)d_in[14];
    const float* b1   = (const float*)d_in[15];
    const float* W2   = (const float*)d_in[16];
    const float* b2   = (const float*)d_in[17];
    const float* ln2g = (const float*)d_in[18];
    const float* ln2b = (const float*)d_in[19];
    const float* lnfg = (const float*)d_in[20];
    const float* lnfb = (const float*)d_in[21];
    const float* headw= (const float*)d_in[22];
    float* out = (float*)d_out;

    float *x, *h, *q, *k, *v, *o, *ff, *nll;
    cudaGetSymbolAddress((void**)&x,   g_x);
    cudaGetSymbolAddress((void**)&h,   g_h);
    cudaGetSymbolAddress((void**)&q,   g_q);
    cudaGetSymbolAddress((void**)&k,   g_k);
    cudaGetSymbolAddress((void**)&v,   g_v);
    cudaGetSymbolAddress((void**)&o,   g_o);
    cudaGetSymbolAddress((void**)&ff,  g_ff);
    cudaGetSymbolAddress((void**)&nll, g_nll);

    embed_k<<<NBS, 256>>>(idx, mask, tok, pos, x);

    dim3 gQKV(ND / 64, NBS / 128, 3);   // 384 CTAs
    dim3 gDD(ND / 64, NBS / 128);       // 128 CTAs
    dim3 gDF(NFF / 128, NBS / 128);     // 256 CTAs
    dim3 gFA(NS / 64, NB * NH);         // 256 CTAs x 256 thr

    for (int l = 0; l < NL; l++) {
        const float* wq = Wq + (size_t)l * ND * ND;
        const float* wk = Wk + (size_t)l * ND * ND;
        const float* wv = Wv + (size_t)l * ND * ND;
        const float* wo = Wo + (size_t)l * ND * ND;
        const float* w1 = W1 + (size_t)l * ND * NFF;
        const float* w2 = W2 + (size_t)l * NFF * ND;

        ln_k<<<NBS, 256>>>(x, ln1g + l * ND, ln1b + l * ND, h);
        TriPtrs t;
        t.w[0] = wq; t.w[1] = wk; t.w[2] = wv;
        t.b[0] = bq + l * ND; t.b[1] = bk + l * ND; t.b[2] = bv + l * ND;
        t.c[0] = q; t.c[1] = k; t.c[2] = v;
        gemm_qkv<<<gQKV, 256>>>(h, t, NBS, ND, ND);
        attn_flash<<<gFA, 256>>>(q, k, v, o);
        gemm_tc<0, true, true, 64, true, false><<<gDD, 256>>>(o, wo, bo + l * ND, x, x, NBS, ND, ND);
        ln_k<<<NBS, 256>>>(x, ln2g + l * ND, ln2b + l * ND, h);
        gemm_tc<1, true, false, 128, true, false><<<gDF, 256>>>(h, w1, b1 + l * NFF, nullptr, ff, NBS, NFF, ND);
        gemm_tc<0, true, true, 64, true, false><<<gDD, 256>>>(ff, w2, b2 + l * ND, x, x, NBS, ND, NFF);
    }

    ln_k<<<NBS, 256>>>(x, lnfg, lnfb, h);
    dim3 gHead(NBS / 128, (NV + 127) / 128);   // M-tiles fastest -> B reused in L2
    gemm_tc<0, false, false, 128, false, true><<<gHead, 256>>>(h, headw, nullptr, nullptr, out, NBS, NV, ND);

    loss_row_k<<<NBS, 512>>>(out, idx, mask, nll);
    loss_final_k<<<1, 1024>>>(nll, out + (size_t)NBS * NV);
}